// round 10
// baseline (speedup 1.0000x reference)
#include <cuda_runtime.h>
#include <cuda_bf16.h>
#include <float.h>
#include <math.h>

// ---------------- problem constants ----------------
#define BB   16
#define EE   400
#define RR   624
#define NN   1024          // E + R
#define HSZ  512
#define HEADS 4
#define DK   128
#define DFF  2048
#define PROP 2
#define RTOKS 40
#define NQKV 1536          // packed QKV output width

// ---------------- scratch (device globals; no allocs allowed) ----------------
__device__ float g_x[(long)BB*NN*HSZ];
__device__ float g_o[(long)BB*NN*HSZ];
__device__ float g_t[(long)BB*NN*HSZ];
__device__ float g_h[(long)BB*NN*DFF];             // also holds QKV [M][1536] transiently
__device__ float g_w[(long)PROP*HSZ*NQKV];         // packed Wq|Wk|Wv per layer
__device__ unsigned g_mask[(long)BB*NN*(NN/32)];   // adj bitmask, 2MB

// ---------------- helpers ----------------
__device__ __forceinline__ unsigned f2tf32(float x) {
    unsigned r;
    asm("cvt.rna.tf32.f32 %0, %1;" : "=r"(r) : "f"(x));
    return r;
}

__device__ __forceinline__ void mma_tf32(float* c, const unsigned* a, unsigned b0, unsigned b1) {
    asm volatile(
        "mma.sync.aligned.m16n8k8.row.col.f32.tf32.tf32.f32 "
        "{%0,%1,%2,%3}, {%4,%5,%6,%7}, {%8,%9}, {%0,%1,%2,%3};\n"
        : "+f"(c[0]), "+f"(c[1]), "+f"(c[2]), "+f"(c[3])
        : "r"(a[0]), "r"(a[1]), "r"(a[2]), "r"(a[3]), "r"(b0), "r"(b1));
}

__device__ __forceinline__ void cp16(unsigned dst, const void* src) {
    asm volatile("cp.async.cg.shared.global [%0], [%1], 16;" :: "r"(dst), "l"(src) : "memory");
}
__device__ __forceinline__ void cp_commit() {
    asm volatile("cp.async.commit_group;" ::: "memory");
}

// ---------------- gather: x = concat(ents, renc[rels]) ----------------
__global__ void __launch_bounds__(256) gather_kernel(
    const float* __restrict__ ents, const int* __restrict__ rels,
    const float* __restrict__ renc)
{
    long i = (long)blockIdx.x * 256 + threadIdx.x;          // float4 index
    const long TOT = (long)BB * NN * (HSZ / 4);
    if (i >= TOT) return;
    int c  = (int)(i & (HSZ/4 - 1));                        // 0..127
    long bn = i >> 7;
    int n  = (int)(bn & (NN - 1));
    int b  = (int)(bn >> 10);
    float4 v;
    if (n < EE) {
        v = ((const float4*)ents)[((long)b*EE + n)*(HSZ/4) + c];
    } else {
        int r = rels[b*RR + (n - EE)];
        v = ((const float4*)renc)[(long)r*(HSZ/4) + c];
    }
    ((float4*)g_x)[i] = v;
}

// ---------------- adj -> bitmask (32 cols per word) ----------------
__global__ void __launch_bounds__(256) mask_kernel(const int* __restrict__ adj)
{
    long i = (long)blockIdx.x * 256 + threadIdx.x;          // word index
    const long TOT = (long)BB * NN * (NN / 32);
    if (i >= TOT) return;
    const int* p = adj + i * 32;
    unsigned m = 0;
    #pragma unroll
    for (int t = 0; t < 8; t++) {
        int4 a = ((const int4*)p)[t];
        m |= (a.x ? 1u : 0u) << (t*4 + 0);
        m |= (a.y ? 1u : 0u) << (t*4 + 1);
        m |= (a.z ? 1u : 0u) << (t*4 + 2);
        m |= (a.w ? 1u : 0u) << (t*4 + 3);
    }
    g_mask[i] = m;
}

// ---------------- pack W: g_w[j][k][n] = [Wq | Wk | Wv] ----------------
__global__ void __launch_bounds__(256) pack_w_kernel(
    const float* __restrict__ Wq, const float* __restrict__ Wk,
    const float* __restrict__ Wv)
{
    long i = (long)blockIdx.x * 256 + threadIdx.x;          // float4 index
    const long TOT = (long)PROP * HSZ * (NQKV/4);
    if (i >= TOT) return;
    int n4 = (int)(i % (NQKV/4));
    long jk = i / (NQKV/4);                                 // j*512 + k
    int n = n4 * 4;
    const float* src;
    if (n < 512)       src = Wq + jk*512 + n;
    else if (n < 1024) src = Wk + jk*512 + (n - 512);
    else               src = Wv + jk*512 + (n - 1024);
    ((float4*)g_w)[i] = *(const float4*)src;
}

// ---------------- fused flash attention (masked) + residual ----------------
// Per block: 128 Q rows for one (b,h). 8 warps, warp w owns rows [w*16, w*16+16).
// Q/K/V are sub-views of [M][ld] with head offset; X/O are [M][HSZ].
#define FL_STRIDE 136
#define FL_WORDS  (128 * FL_STRIDE)
#define FL_BYTES  (3 * FL_WORDS * 4)
#define FL_NT     (NN / 128)

__global__ void __launch_bounds__(256) flash_kernel(
    const float* __restrict__ QKV, int ld,
    const float* __restrict__ X, float* __restrict__ O)
{
    extern __shared__ unsigned sm[];
    unsigned* sQ   = sm;
    unsigned* bufK = sm + FL_WORDS;
    unsigned* bufV = sm + 2 * FL_WORDS;
    unsigned sbase = (unsigned)__cvta_generic_to_shared(sm);

    int qt = blockIdx.x, h = blockIdx.y, b = blockIdx.z;
    int tid = threadIdx.x, warp = tid >> 5, lane = tid & 31;
    int gid = lane >> 2, tig = lane & 3;

    const float scale = 0.04419417382415922f;  // 1/sqrt(512)
    const long baserow = (long)b * NN;
    const int  hc = h * DK;

    const float* Q = QKV;
    const float* Kbase = QKV + 512 + baserow * ld + hc;
    const float* Vbase = QKV + 1024 + baserow * ld + hc;

    auto cp_tile = [&](unsigned dstW, const float* src) {
        #pragma unroll
        for (int t = 0; t < 16; t++) {
            int i = tid + t * 256;
            int r = i >> 5, c4 = (i & 31) << 2;
            cp16(sbase + (dstW + r * FL_STRIDE + c4) * 4, src + (long)r * ld + c4);
        }
    };

    cp_tile(FL_WORDS, Kbase);                cp_commit();     // G0 = K0
    cp_tile(2 * FL_WORDS, Vbase);            cp_commit();     // G1 = V0

    {
        const float* src = Q + (baserow + qt*128) * ld + hc;
        for (int i = tid; i < 128*32; i += 256) {
            int r = i >> 5, c4 = (i & 31) * 4;
            float4 v = *(const float4*)(src + (long)r * ld + c4);
            unsigned* d = &sQ[r * FL_STRIDE + c4];
            d[0] = f2tf32(v.x * scale); d[1] = f2tf32(v.y * scale);
            d[2] = f2tf32(v.z * scale); d[3] = f2tf32(v.w * scale);
        }
    }

    float acc_o[16][4];
    #pragma unroll
    for (int nt = 0; nt < 16; nt++)
        #pragma unroll
        for (int i = 0; i < 4; i++) acc_o[nt][i] = 0.f;

    float m0 = -INFINITY, m1 = -INFINITY, l0 = 0.f, l1 = 0.f;

    const unsigned* mrow0 = g_mask + ((long)b*NN + qt*128 + warp*16 + gid) * (NN/32);
    const unsigned* mrow1 = mrow0 + 8 * (NN/32);

    float acc_s[16][4];

    for (int j = 0; j < FL_NT; j++) {
        asm volatile("cp.async.wait_group 1;" ::: "memory");
        __syncthreads();

        #pragma unroll
        for (int nt = 0; nt < 16; nt++)
            #pragma unroll
            for (int i = 0; i < 4; i++) acc_s[nt][i] = 0.f;

        #pragma unroll
        for (int ks = 0; ks < 16; ks++) {
            int k0 = ks * 8;
            unsigned a[4];
            const unsigned* ap = &sQ[(warp*16 + gid) * FL_STRIDE + k0 + tig];
            a[0] = ap[0]; a[1] = ap[8*FL_STRIDE]; a[2] = ap[4]; a[3] = ap[8*FL_STRIDE + 4];
            #pragma unroll
            for (int nt = 0; nt < 16; nt++) {
                const unsigned* bp = &bufK[(nt*8 + gid) * FL_STRIDE + k0 + tig];
                mma_tf32(acc_s[nt], a, bp[0], bp[4]);
            }
        }

        __syncthreads();
        if (j + 1 < FL_NT) {
            cp_tile(FL_WORDS, Kbase + (long)(j+1)*128 * ld);
            cp_commit();
        }

        unsigned mw0[4], mw1[4];
        #pragma unroll
        for (int w = 0; w < 4; w++) { mw0[w] = mrow0[j*4 + w]; mw1[w] = mrow1[j*4 + w]; }

        float tm0 = -INFINITY, tm1 = -INFINITY;
        #pragma unroll
        for (int nt = 0; nt < 16; nt++) {
            int c0 = nt*8 + tig*2;
            unsigned w = nt >> 2;
            int bi = c0 & 31;
            acc_s[nt][0] = ((mw0[w] >> bi)     & 1) ? acc_s[nt][0] : -1e30f;
            acc_s[nt][1] = ((mw0[w] >> (bi+1)) & 1) ? acc_s[nt][1] : -1e30f;
            acc_s[nt][2] = ((mw1[w] >> bi)     & 1) ? acc_s[nt][2] : -1e30f;
            acc_s[nt][3] = ((mw1[w] >> (bi+1)) & 1) ? acc_s[nt][3] : -1e30f;
            tm0 = fmaxf(tm0, fmaxf(acc_s[nt][0], acc_s[nt][1]));
            tm1 = fmaxf(tm1, fmaxf(acc_s[nt][2], acc_s[nt][3]));
        }
        tm0 = fmaxf(tm0, __shfl_xor_sync(0xffffffffu, tm0, 1));
        tm0 = fmaxf(tm0, __shfl_xor_sync(0xffffffffu, tm0, 2));
        tm1 = fmaxf(tm1, __shfl_xor_sync(0xffffffffu, tm1, 1));
        tm1 = fmaxf(tm1, __shfl_xor_sync(0xffffffffu, tm1, 2));

        float nm0 = fmaxf(m0, tm0), nm1 = fmaxf(m1, tm1);
        float f0 = __expf(m0 - nm0), f1 = __expf(m1 - nm1);

        float sum0 = 0.f, sum1 = 0.f;
        #pragma unroll
        for (int nt = 0; nt < 16; nt++) {
            float p0 = __expf(acc_s[nt][0] - nm0);
            float p1 = __expf(acc_s[nt][1] - nm0);
            float p2 = __expf(acc_s[nt][2] - nm1);
            float p3 = __expf(acc_s[nt][3] - nm1);
            sum0 += p0 + p1; sum1 += p2 + p3;
            acc_s[nt][0] = p0; acc_s[nt][1] = p1;
            acc_s[nt][2] = p2; acc_s[nt][3] = p3;
        }
        sum0 += __shfl_xor_sync(0xffffffffu, sum0, 1);
        sum0 += __shfl_xor_sync(0xffffffffu, sum0, 2);
        sum1 += __shfl_xor_sync(0xffffffffu, sum1, 1);
        sum1 += __shfl_xor_sync(0xffffffffu, sum1, 2);

        l0 = l0 * f0 + sum0;  l1 = l1 * f1 + sum1;
        m0 = nm0;  m1 = nm1;
        #pragma unroll
        for (int nt = 0; nt < 16; nt++) {
            acc_o[nt][0] *= f0; acc_o[nt][1] *= f0;
            acc_o[nt][2] *= f1; acc_o[nt][3] *= f1;
        }

        if (j + 1 < FL_NT) asm volatile("cp.async.wait_group 1;" ::: "memory");
        else               asm volatile("cp.async.wait_group 0;" ::: "memory");
        __syncthreads();

        const int s0 = tig >> 1;
        const bool odd = (tig & 1);
        #pragma unroll
        for (int ks = 0; ks < 16; ks++) {
            float p0 = acc_s[ks][0], p1 = acc_s[ks][1];
            float p2 = acc_s[ks][2], p3 = acc_s[ks][3];
            float q0a = __shfl_sync(0xffffffffu, p0, s0, 4);
            float q0b = __shfl_sync(0xffffffffu, p1, s0, 4);
            float q1a = __shfl_sync(0xffffffffu, p2, s0, 4);
            float q1b = __shfl_sync(0xffffffffu, p3, s0, 4);
            float q2a = __shfl_sync(0xffffffffu, p0, s0 + 2, 4);
            float q2b = __shfl_sync(0xffffffffu, p1, s0 + 2, 4);
            float q3a = __shfl_sync(0xffffffffu, p2, s0 + 2, 4);
            float q3b = __shfl_sync(0xffffffffu, p3, s0 + 2, 4);
            unsigned a[4];
            a[0] = f2tf32(odd ? q0b : q0a);
            a[1] = f2tf32(odd ? q1b : q1a);
            a[2] = f2tf32(odd ? q2b : q2a);
            a[3] = f2tf32(odd ? q3b : q3a);

            int k0 = ks * 8;
            #pragma unroll
            for (int nt = 0; nt < 16; nt++) {
                const unsigned* bp = &bufV[(k0 + tig) * FL_STRIDE + nt*8 + gid];
                mma_tf32(acc_o[nt], a, bp[0], bp[4*FL_STRIDE]);
            }
        }

        if (j + 1 < FL_NT) {
            __syncthreads();
            cp_tile(2 * FL_WORDS, Vbase + (long)(j+1)*128 * ld);
            cp_commit();
        }
    }

    float inv0 = 1.f / l0, inv1 = 1.f / l1;
    long rbase = (baserow + qt*128 + warp*16 + gid) * HSZ + hc;
    #pragma unroll
    for (int nt = 0; nt < 16; nt++) {
        int c0 = nt*8 + tig*2;
        float2 x0 = *(const float2*)(X + rbase + c0);
        float2 x1 = *(const float2*)(X + rbase + 8*HSZ + c0);
        float2 o0 = make_float2(acc_o[nt][0]*inv0 + x0.x, acc_o[nt][1]*inv0 + x0.y);
        float2 o1 = make_float2(acc_o[nt][2]*inv1 + x1.x, acc_o[nt][3]*inv1 + x1.y);
        *(float2*)(O + rbase + c0)           = o0;
        *(float2*)(O + rbase + 8*HSZ + c0)   = o1;
    }
}

// ---------------- tf32 GEMM v2: pair-interleaved smem, LDS.64 fragments ----------------
// C[m][n] = sum_k A[m][k] * B[k][n]  (+bias)(prelu)(+res). 128x128 tile, k-chunk 32.
// A pairs: word(row,k) = row*40 + (k>>3)*8 + (k&3)*2 + ((k>>2)&1)
// B pairs: word(k,n)   = ((k>>3)*4 + (k&3))*264 + n*2 + ((k>>2)&1)
__global__ void __launch_bounds__(256, 2) gemm_mma(
    const float* __restrict__ A, const float* __restrict__ B, float* __restrict__ C,
    int N, int K, int lda, int ldb, int ldc,
    const float* __restrict__ bias,
    const float* __restrict__ prelu,
    const float* __restrict__ res)
{
    constexpr int PA  = 40;    // words per A row
    constexpr int PBR = 264;   // words per B pair-row

    __shared__ unsigned As[128 * PA];   // 20.0 KB
    __shared__ unsigned Bs[16 * PBR];   // 16.5 KB

    int bm = blockIdx.y << 7;
    int bn = blockIdx.x << 7;

    int tid  = threadIdx.x;
    int warp = tid >> 5, lane = tid & 31;
    int wm = warp >> 1, wn = warp & 1;          // 4x2 warp grid, warp tile 32x64
    int gid = lane >> 2, tig = lane & 3;

    float acc[2][8][4];
    #pragma unroll
    for (int mt = 0; mt < 2; mt++)
        #pragma unroll
        for (int nt = 0; nt < 8; nt++)
            #pragma unroll
            for (int i = 0; i < 4; i++) acc[mt][nt][i] = 0.f;

    // staging decomposition
    const int arow = tid >> 1;                  // 0..127
    const int akb  = (tid & 1) << 4;            // 0 or 16
    const int bpr  = tid >> 4;                  // 0..15 pair-row
    const int bk   = (bpr >> 2) * 8 + (bpr & 3);// source k within chunk
    const int bcol = (tid & 15) << 3;           // 0..120

    const float* pa = A + (long)(bm + arow) * lda + akb;
    const float* pb = B + (long)bk * ldb + bn + bcol;
    const long pbs = 4L * ldb;

    float4 ra0, ra1, ra2, ra3, rb0, rb1, rb2, rb3;
    const int nch = K >> 5;

    // load chunk 0
    ra0 = *(const float4*)(pa);      ra1 = *(const float4*)(pa + 4);
    ra2 = *(const float4*)(pa + 8);  ra3 = *(const float4*)(pa + 12);
    rb0 = *(const float4*)(pb);      rb1 = *(const float4*)(pb + 4);
    rb2 = *(const float4*)(pb + pbs); rb3 = *(const float4*)(pb + pbs + 4);

    unsigned* aw = &As[arow * PA + (akb >> 3) * 8];
    unsigned* bw = &Bs[bpr * PBR + bcol * 2];

    for (int c = 0; c < nch; c++) {
        // ---- store staged chunk (tf32, pair-interleaved) ----
        uint4 u;
        u.x = f2tf32(ra0.x); u.y = f2tf32(ra1.x); u.z = f2tf32(ra0.y); u.w = f2tf32(ra1.y);
        *(uint4*)&aw[0] = u;
        u.x = f2tf32(ra0.z); u.y = f2tf32(ra1.z); u.z = f2tf32(ra0.w); u.w = f2tf32(ra1.w);
        *(uint4*)&aw[4] = u;
        u.x = f2tf32(ra2.x); u.y = f2tf32(ra3.x); u.z = f2tf32(ra2.y); u.w = f2tf32(ra3.y);
        *(uint4*)&aw[8] = u;
        u.x = f2tf32(ra2.z); u.y = f2tf32(ra3.z); u.z = f2tf32(ra2.w); u.w = f2tf32(ra3.w);
        *(uint4*)&aw[12] = u;

        u.x = f2tf32(rb0.x); u.y = f2tf32(rb2.x); u.z = f2tf32(rb0.y); u.w = f2tf32(rb2.y);
        *(uint4*)&bw[0] = u;
        u.x = f2tf32(rb0.z); u.y = f2tf32(rb2.z); u.z = f2tf32(rb0.w); u.w = f2tf32(rb2.w);
        *(uint4*)&bw[4] = u;
        u.x = f2tf32(rb1.x); u.y = f2tf32(rb3.x); u.z = f2tf32(rb1.y); u.w = f2tf32(rb3.y);
        *(uint4*)&bw[8] = u;
        u.x = f2tf32(rb1.z); u.y = f2tf32(rb3.z); u.z = f2tf32(rb1.w); u.w = f2tf32(rb3.w);
        *(uint4*)&bw[12] = u;
        __syncthreads();

        // ---- prefetch next chunk ----
        if (c + 1 < nch) {
            pa += 32;
            pb += 32L * ldb;
            ra0 = *(const float4*)(pa);      ra1 = *(const float4*)(pa + 4);
            ra2 = *(const float4*)(pa + 8);  ra3 = *(const float4*)(pa + 12);
            rb0 = *(const float4*)(pb);      rb1 = *(const float4*)(pb + 4);
            rb2 = *(const float4*)(pb + pbs); rb3 = *(const float4*)(pb + pbs + 4);
        }

        // ---- compute: 4 ks x (4 LDS.64 A + 8 LDS.64 B + 16 mma) ----
        #pragma unroll
        for (int ks = 0; ks < 4; ks++) {
            const unsigned* ap = &As[(wm*32 + gid) * PA + ks*8 + tig*2];
            uint2 a0  = *(const uint2*)(ap);
            uint2 a1  = *(const uint2*)(ap + 8*PA);
            uint2 a0b = *(const uint2*)(ap + 16*PA);
            uint2 a1b = *(const uint2*)(ap + 24*PA);
            unsigned af0[4] = { a0.x, a1.x, a0.y, a1.y };
            unsigned af1[4] = { a0b.x, a1b.x, a0b.y, a1b.y };

            const unsigned* bbase = &Bs[(ks*4 + tig) * PBR + (wn*64 + gid) * 2];
            #pragma unroll
            for (int nt = 0; nt < 8; nt++) {
                uint2 bf = *(const uint2*)(bbase + nt*16);
                mma_tf32(acc[0][nt], af0, bf.x, bf.y);
                mma_tf32(acc[1][nt], af1, bf.x, bf.y);
            }
        }
        if (c + 1 < nch) __syncthreads();
    }

    // ---- epilogue ----
    #pragma unroll
    for (int mt = 0; mt < 2; mt++) {
        int r0 = bm + wm * 32 + mt * 16 + gid;
        #pragma unroll
        for (int nt = 0; nt < 8; nt++) {
            int c0 = bn + wn * 64 + nt * 8 + tig * 2;
            float v0 = acc[mt][nt][0];
            float v1 = acc[mt][nt][1];
            float v2 = acc[mt][nt][2];
            float v3 = acc[mt][nt][3];
            if (bias) {
                float b0v = bias[c0], b1v = bias[c0 + 1];
                v0 += b0v; v1 += b1v; v2 += b0v; v3 += b1v;
            }
            if (prelu) {
                float p0 = prelu[c0], p1 = prelu[c0 + 1];
                v0 = v0 > 0.f ? v0 : v0 * p0;
                v1 = v1 > 0.f ? v1 : v1 * p1;
                v2 = v2 > 0.f ? v2 : v2 * p0;
                v3 = v3 > 0.f ? v3 : v3 * p1;
            }
            if (res) {
                float2 q0 = *(const float2*)(res + (long)r0 * ldc + c0);
                float2 q1 = *(const float2*)(res + (long)(r0 + 8) * ldc + c0);
                v0 += q0.x; v1 += q0.y; v2 += q1.x; v3 += q1.y;
            }
            *(float2*)(C + (long)r0 * ldc + c0)       = make_float2(v0, v1);
            *(float2*)(C + (long)(r0 + 8) * ldc + c0) = make_float2(v2, v3);
        }
    }
}

// ---------------- layer norm over rows of 512 ----------------
__global__ void __launch_bounds__(128) layernorm_kernel(
    const float* __restrict__ in, float* __restrict__ out,
    const float* __restrict__ gamma, const float* __restrict__ beta)
{
    long row = blockIdx.x;
    int tid = threadIdx.x, lane = tid & 31, wid = tid >> 5;
    float4 v = ((const float4*)(in + row * HSZ))[tid];

    __shared__ float red[8];
    float s = v.x + v.y + v.z + v.w;
    #pragma unroll
    for (int o = 16; o > 0; o >>= 1) s += __shfl_xor_sync(0xffffffffu, s, o);
    if (lane == 0) red[wid] = s;
    __syncthreads();
    float mu = (red[0] + red[1] + red[2] + red[3]) * (1.f / HSZ);

    float dx = v.x - mu, dy = v.y - mu, dz = v.z - mu, dw = v.w - mu;
    float q = dx*dx + dy*dy + dz*dz + dw*dw;
    #pragma unroll
    for (int o = 16; o > 0; o >>= 1) q += __shfl_xor_sync(0xffffffffu, q, o);
    if (lane == 0) red[4 + wid] = q;
    __syncthreads();
    float var = (red[4] + red[5] + red[6] + red[7]) * (1.f / HSZ);
    float rstd = rsqrtf(var + 1e-5f);

    float4 g = ((const float4*)gamma)[tid];
    float4 bb = ((const float4*)beta)[tid];
    float4 o4;
    o4.x = dx * rstd * g.x + bb.x;
    o4.y = dy * rstd * g.y + bb.y;
    o4.z = dz * rstd * g.z + bb.z;
    o4.w = dw * rstd * g.w + bb.w;
    ((float4*)(out + row * HSZ))[tid] = o4;
}

// ---------------- output assembly: [glob | nodes | mask] ----------------
__global__ void __launch_bounds__(256) write_out_kernel(float* __restrict__ out, long out_size)
{
    long i = (long)blockIdx.x * 256 + threadIdx.x;
    if (i >= out_size) return;
    const long G  = (long)BB * HSZ;                 // 8192
    const long ND = (long)BB * NN * HSZ;            // 8388608
    if (i < G) {
        long b = i >> 9;
        long c = i & 511;
        out[i] = g_x[(b * NN + EE) * HSZ + c];
    } else if (i < G + ND) {
        out[i] = g_x[i - G];
    } else {
        out[i] = 1.0f;
    }
}

// ---------------- orchestration ----------------
extern "C" void kernel_launch(void* const* d_in, const int* in_sizes, int n_in,
                              void* d_out, int out_size)
{
    const float* ents = (const float*)d_in[0];
    const int*   rels = (const int*)  d_in[1];
    const int*   adj  = (const int*)  d_in[2];
    const float* renc = (const float*)d_in[3];
    const float* Wq   = (const float*)d_in[4];
    const float* Wk   = (const float*)d_in[5];
    const float* Wv   = (const float*)d_in[6];
    const float* l1w  = (const float*)d_in[7];
    const float* l1b  = (const float*)d_in[8];
    const float* l2w  = (const float*)d_in[9];
    const float* l2b  = (const float*)d_in[10];
    const float* ln1s = (const float*)d_in[11];
    const float* ln1b = (const float*)d_in[12];
    const float* ln2s = (const float*)d_in[13];
    const float* ln2b = (const float*)d_in[14];
    const float* pa   = (const float*)d_in[15];

    float *gx, *go, *gt, *gh, *gw;
    cudaGetSymbolAddress((void**)&gx, g_x);
    cudaGetSymbolAddress((void**)&go, g_o);
    cudaGetSymbolAddress((void**)&gt, g_t);
    cudaGetSymbolAddress((void**)&gh, g_h);
    cudaGetSymbolAddress((void**)&gw, g_w);

    cudaFuncSetAttribute(flash_kernel, cudaFuncAttributeMaxDynamicSharedMemorySize, FL_BYTES);

    const long M = (long)BB * NN;                   // 16384

    // gather x
    {
        long tot = M * (HSZ/4);
        gather_kernel<<<(unsigned)((tot + 255) / 256), 256>>>(ents, rels, renc);
    }
    // adj -> bitmask (once)
    {
        long tot = (long)BB * NN * (NN/32);
        mask_kernel<<<(unsigned)((tot + 255) / 256), 256>>>(adj);
    }
    // pack QKV weights (once)
    {
        long tot = (long)PROP * HSZ * (NQKV/4);
        pack_w_kernel<<<(unsigned)((tot + 255) / 256), 256>>>(Wq, Wk, Wv);
    }

    for (int j = 0; j < PROP; j++) {
        // [Q|K|V] = x @ [Wq|Wk|Wv]  -> g_h as [M][1536]
        gemm_mma<<<dim3(NQKV/128, (unsigned)(M/128)), 256>>>(
            gx, gw + (long)j*HSZ*NQKV, gh, NQKV, HSZ, HSZ, NQKV, NQKV,
            nullptr, nullptr, nullptr);

        // fused attention + residual -> g_o
        flash_kernel<<<dim3(NN/128, HEADS, BB), 256, FL_BYTES>>>(gh, NQKV, gx, go);

        // t = LN1(out)
        layernorm_kernel<<<(unsigned)M, 128>>>(go, gt, ln1s + j*HSZ, ln1b + j*HSZ);

        // h = prelu(t @ l1_w + l1_b) -> g_h as [M][2048]
        gemm_mma<<<dim3(DFF/128, (unsigned)(M/128)), 256>>>(
            gt, l1w + (long)j*HSZ*DFF, gh, DFF, HSZ, HSZ, DFF, DFF,
            l1b + (long)j*DFF, pa + (long)j*DFF, nullptr);

        // o = h @ l2_w + l2_b + t
        gemm_mma<<<dim3(HSZ/128, (unsigned)(M/128)), 256>>>(
            gh, l2w + (long)j*DFF*HSZ, go, HSZ, DFF, DFF, HSZ, HSZ,
            l2b + (long)j*HSZ, nullptr, gt);

        // x = LN2(o)
        layernorm_kernel<<<(unsigned)M, 128>>>(go, gx, ln2s + j*HSZ, ln2b + j*HSZ);
    }

    // assemble output
    {
        long os = (long)out_size;
        write_out_kernel<<<(unsigned)((os + 255) / 256), 256>>>((float*)d_out, os);
    }
}

// round 11
// speedup vs baseline: 1.4676x; 1.4676x over previous
#include <cuda_runtime.h>
#include <cuda_bf16.h>
#include <float.h>
#include <math.h>

// ---------------- problem constants ----------------
#define BB   16
#define EE   400
#define RR   624
#define NN   1024          // E + R
#define HSZ  512
#define HEADS 4
#define DK   128
#define DFF  2048
#define PROP 2
#define RTOKS 40
#define NQKV 1536          // packed QKV output width

// ---------------- scratch (device globals; no allocs allowed) ----------------
__device__ float g_x[(long)BB*NN*HSZ];
__device__ float g_o[(long)BB*NN*HSZ];
__device__ float g_t[(long)BB*NN*HSZ];
__device__ float g_h[(long)BB*NN*DFF];             // also holds QKV [M][1536] transiently
__device__ float g_w[(long)PROP*HSZ*NQKV];         // packed tf32-rounded Wq|Wk|Wv
__device__ float g_w1[(long)PROP*HSZ*DFF];         // tf32-rounded l1_w
__device__ float g_w2[(long)PROP*DFF*HSZ];         // tf32-rounded l2_w
__device__ unsigned g_mask[(long)BB*NN*(NN/32)];   // adj bitmask, 2MB

// ---------------- helpers ----------------
__device__ __forceinline__ unsigned f2tf32(float x) {
    unsigned r;
    asm("cvt.rna.tf32.f32 %0, %1;" : "=r"(r) : "f"(x));
    return r;
}
__device__ __forceinline__ float f2tf32f(float x) {
    return __uint_as_float(f2tf32(x));
}

__device__ __forceinline__ void mma_tf32(float* c, const unsigned* a, unsigned b0, unsigned b1) {
    asm volatile(
        "mma.sync.aligned.m16n8k8.row.col.f32.tf32.tf32.f32 "
        "{%0,%1,%2,%3}, {%4,%5,%6,%7}, {%8,%9}, {%0,%1,%2,%3};\n"
        : "+f"(c[0]), "+f"(c[1]), "+f"(c[2]), "+f"(c[3])
        : "r"(a[0]), "r"(a[1]), "r"(a[2]), "r"(a[3]), "r"(b0), "r"(b1));
}

__device__ __forceinline__ void cp16(unsigned dst, const void* src) {
    asm volatile("cp.async.cg.shared.global [%0], [%1], 16;" :: "r"(dst), "l"(src) : "memory");
}
__device__ __forceinline__ void cp_commit() {
    asm volatile("cp.async.commit_group;" ::: "memory");
}

// ---------------- gather: x = concat(ents, renc[rels]), tf32-rounded ----------------
__global__ void __launch_bounds__(256) gather_kernel(
    const float* __restrict__ ents, const int* __restrict__ rels,
    const float* __restrict__ renc)
{
    long i = (long)blockIdx.x * 256 + threadIdx.x;          // float4 index
    const long TOT = (long)BB * NN * (HSZ / 4);
    if (i >= TOT) return;
    int c  = (int)(i & (HSZ/4 - 1));                        // 0..127
    long bn = i >> 7;
    int n  = (int)(bn & (NN - 1));
    int b  = (int)(bn >> 10);
    float4 v;
    if (n < EE) {
        v = ((const float4*)ents)[((long)b*EE + n)*(HSZ/4) + c];
    } else {
        int r = rels[b*RR + (n - EE)];
        v = ((const float4*)renc)[(long)r*(HSZ/4) + c];
    }
    v.x = f2tf32f(v.x); v.y = f2tf32f(v.y); v.z = f2tf32f(v.z); v.w = f2tf32f(v.w);
    ((float4*)g_x)[i] = v;
}

// ---------------- adj -> bitmask (32 cols per word) ----------------
__global__ void __launch_bounds__(256) mask_kernel(const int* __restrict__ adj)
{
    long i = (long)blockIdx.x * 256 + threadIdx.x;          // word index
    const long TOT = (long)BB * NN * (NN / 32);
    if (i >= TOT) return;
    const int* p = adj + i * 32;
    unsigned m = 0;
    #pragma unroll
    for (int t = 0; t < 8; t++) {
        int4 a = ((const int4*)p)[t];
        m |= (a.x ? 1u : 0u) << (t*4 + 0);
        m |= (a.y ? 1u : 0u) << (t*4 + 1);
        m |= (a.z ? 1u : 0u) << (t*4 + 2);
        m |= (a.w ? 1u : 0u) << (t*4 + 3);
    }
    g_mask[i] = m;
}

// ---------------- pack W: g_w[j][k][n] = tf32([Wq | Wk | Wv]) ----------------
__global__ void __launch_bounds__(256) pack_w_kernel(
    const float* __restrict__ Wq, const float* __restrict__ Wk,
    const float* __restrict__ Wv)
{
    long i = (long)blockIdx.x * 256 + threadIdx.x;          // float4 index
    const long TOT = (long)PROP * HSZ * (NQKV/4);
    if (i >= TOT) return;
    int n4 = (int)(i % (NQKV/4));
    long jk = i / (NQKV/4);                                 // j*512 + k
    int n = n4 * 4;
    const float* src;
    if (n < 512)       src = Wq + jk*512 + n;
    else if (n < 1024) src = Wk + jk*512 + (n - 512);
    else               src = Wv + jk*512 + (n - 1024);
    float4 v = *(const float4*)src;
    v.x = f2tf32f(v.x); v.y = f2tf32f(v.y); v.z = f2tf32f(v.z); v.w = f2tf32f(v.w);
    ((float4*)g_w)[i] = v;
}

// ---------------- round FFN weights to tf32 copies ----------------
__global__ void __launch_bounds__(256) pack_ffn_kernel(
    const float* __restrict__ l1w, const float* __restrict__ l2w)
{
    long i = (long)blockIdx.x * 256 + threadIdx.x;          // float4 index
    const long TOT = (long)PROP * HSZ * DFF / 4;
    if (i >= TOT) return;
    float4 a = ((const float4*)l1w)[i];
    a.x = f2tf32f(a.x); a.y = f2tf32f(a.y); a.z = f2tf32f(a.z); a.w = f2tf32f(a.w);
    ((float4*)g_w1)[i] = a;
    float4 b = ((const float4*)l2w)[i];
    b.x = f2tf32f(b.x); b.y = f2tf32f(b.y); b.z = f2tf32f(b.z); b.w = f2tf32f(b.w);
    ((float4*)g_w2)[i] = b;
}

// ---------------- fused flash attention (masked) + residual ----------------
// Per block: 128 Q rows for one (b,h). 8 warps, warp w owns rows [w*16, w*16+16).
// sQ/bufK stride 132 words (bank = 4*gid+tig, conflict-free row-frag loads),
// bufV stride 136 (bank = 8*tig+gid, conflict-free col-frag loads).
#define FK_STR 132
#define FV_STR 136
#define FL_QW  (128 * FK_STR)
#define FL_KW  (128 * FK_STR)
#define FL_VW  (128 * FV_STR)
#define FL_BYTES ((FL_QW + FL_KW + FL_VW) * 4)
#define FL_NT  (NN / 128)

__global__ void __launch_bounds__(256) flash_kernel(
    const float* __restrict__ QKV, int ld,
    const float* __restrict__ X, float* __restrict__ O)
{
    extern __shared__ unsigned sm[];
    unsigned* sQ   = sm;
    unsigned* bufK = sm + FL_QW;
    unsigned* bufV = sm + FL_QW + FL_KW;
    unsigned sbase = (unsigned)__cvta_generic_to_shared(sm);

    int qt = blockIdx.x, h = blockIdx.y, b = blockIdx.z;
    int tid = threadIdx.x, warp = tid >> 5, lane = tid & 31;
    int gid = lane >> 2, tig = lane & 3;

    const float scale = 0.04419417382415922f;  // 1/sqrt(512)
    const long baserow = (long)b * NN;
    const int  hc = h * DK;

    const float* Q = QKV;
    const float* Kbase = QKV + 512 + baserow * ld + hc;
    const float* Vbase = QKV + 1024 + baserow * ld + hc;

    auto cp_tile = [&](unsigned dstW, const float* src, int sstr) {
        #pragma unroll
        for (int t = 0; t < 16; t++) {
            int i = tid + t * 256;
            int r = i >> 5, c4 = (i & 31) << 2;
            cp16(sbase + (dstW + r * sstr + c4) * 4, src + (long)r * ld + c4);
        }
    };

    cp_tile(FL_QW, Kbase, FK_STR);                 cp_commit();     // G0 = K0
    cp_tile(FL_QW + FL_KW, Vbase, FV_STR);         cp_commit();     // G1 = V0

    {
        const float* src = Q + (baserow + qt*128) * ld + hc;
        for (int i = tid; i < 128*32; i += 256) {
            int r = i >> 5, c4 = (i & 31) * 4;
            float4 v = *(const float4*)(src + (long)r * ld + c4);
            uint4 u;
            u.x = f2tf32(v.x * scale); u.y = f2tf32(v.y * scale);
            u.z = f2tf32(v.z * scale); u.w = f2tf32(v.w * scale);
            *(uint4*)&sQ[r * FK_STR + c4] = u;
        }
    }

    float acc_o[16][4];
    #pragma unroll
    for (int nt = 0; nt < 16; nt++)
        #pragma unroll
        for (int i = 0; i < 4; i++) acc_o[nt][i] = 0.f;

    float m0 = -INFINITY, m1 = -INFINITY, l0 = 0.f, l1 = 0.f;

    const unsigned* mrow0 = g_mask + ((long)b*NN + qt*128 + warp*16 + gid) * (NN/32);
    const unsigned* mrow1 = mrow0 + 8 * (NN/32);

    float acc_s[16][4];

    for (int j = 0; j < FL_NT; j++) {
        asm volatile("cp.async.wait_group 1;" ::: "memory");
        __syncthreads();

        #pragma unroll
        for (int nt = 0; nt < 16; nt++)
            #pragma unroll
            for (int i = 0; i < 4; i++) acc_s[nt][i] = 0.f;

        #pragma unroll
        for (int ks = 0; ks < 16; ks++) {
            int k0 = ks * 8;
            unsigned a[4];
            const unsigned* ap = &sQ[(warp*16 + gid) * FK_STR + k0 + tig];
            a[0] = ap[0]; a[1] = ap[8*FK_STR]; a[2] = ap[4]; a[3] = ap[8*FK_STR + 4];
            #pragma unroll
            for (int nt = 0; nt < 16; nt++) {
                const unsigned* bp = &bufK[(nt*8 + gid) * FK_STR + k0 + tig];
                mma_tf32(acc_s[nt], a, bp[0], bp[4]);
            }
        }

        __syncthreads();
        if (j + 1 < FL_NT) {
            cp_tile(FL_QW, Kbase + (long)(j+1)*128 * ld, FK_STR);
            cp_commit();
        }

        unsigned mw0[4], mw1[4];
        #pragma unroll
        for (int w = 0; w < 4; w++) { mw0[w] = mrow0[j*4 + w]; mw1[w] = mrow1[j*4 + w]; }

        float tm0 = -INFINITY, tm1 = -INFINITY;
        #pragma unroll
        for (int nt = 0; nt < 16; nt++) {
            int c0 = nt*8 + tig*2;
            unsigned w = nt >> 2;
            int bi = c0 & 31;
            acc_s[nt][0] = ((mw0[w] >> bi)     & 1) ? acc_s[nt][0] : -1e30f;
            acc_s[nt][1] = ((mw0[w] >> (bi+1)) & 1) ? acc_s[nt][1] : -1e30f;
            acc_s[nt][2] = ((mw1[w] >> bi)     & 1) ? acc_s[nt][2] : -1e30f;
            acc_s[nt][3] = ((mw1[w] >> (bi+1)) & 1) ? acc_s[nt][3] : -1e30f;
            tm0 = fmaxf(tm0, fmaxf(acc_s[nt][0], acc_s[nt][1]));
            tm1 = fmaxf(tm1, fmaxf(acc_s[nt][2], acc_s[nt][3]));
        }
        tm0 = fmaxf(tm0, __shfl_xor_sync(0xffffffffu, tm0, 1));
        tm0 = fmaxf(tm0, __shfl_xor_sync(0xffffffffu, tm0, 2));
        tm1 = fmaxf(tm1, __shfl_xor_sync(0xffffffffu, tm1, 1));
        tm1 = fmaxf(tm1, __shfl_xor_sync(0xffffffffu, tm1, 2));

        float nm0 = fmaxf(m0, tm0), nm1 = fmaxf(m1, tm1);
        float f0 = __expf(m0 - nm0), f1 = __expf(m1 - nm1);

        float sum0 = 0.f, sum1 = 0.f;
        #pragma unroll
        for (int nt = 0; nt < 16; nt++) {
            float p0 = __expf(acc_s[nt][0] - nm0);
            float p1 = __expf(acc_s[nt][1] - nm0);
            float p2 = __expf(acc_s[nt][2] - nm1);
            float p3 = __expf(acc_s[nt][3] - nm1);
            sum0 += p0 + p1; sum1 += p2 + p3;
            acc_s[nt][0] = p0; acc_s[nt][1] = p1;
            acc_s[nt][2] = p2; acc_s[nt][3] = p3;
        }
        sum0 += __shfl_xor_sync(0xffffffffu, sum0, 1);
        sum0 += __shfl_xor_sync(0xffffffffu, sum0, 2);
        sum1 += __shfl_xor_sync(0xffffffffu, sum1, 1);
        sum1 += __shfl_xor_sync(0xffffffffu, sum1, 2);

        l0 = l0 * f0 + sum0;  l1 = l1 * f1 + sum1;
        m0 = nm0;  m1 = nm1;
        #pragma unroll
        for (int nt = 0; nt < 16; nt++) {
            acc_o[nt][0] *= f0; acc_o[nt][1] *= f0;
            acc_o[nt][2] *= f1; acc_o[nt][3] *= f1;
        }

        if (j + 1 < FL_NT) asm volatile("cp.async.wait_group 1;" ::: "memory");
        else               asm volatile("cp.async.wait_group 0;" ::: "memory");
        __syncthreads();

        const int s0 = tig >> 1;
        const bool odd = (tig & 1);
        #pragma unroll
        for (int ks = 0; ks < 16; ks++) {
            float p0 = acc_s[ks][0], p1 = acc_s[ks][1];
            float p2 = acc_s[ks][2], p3 = acc_s[ks][3];
            float q0a = __shfl_sync(0xffffffffu, p0, s0, 4);
            float q0b = __shfl_sync(0xffffffffu, p1, s0, 4);
            float q1a = __shfl_sync(0xffffffffu, p2, s0, 4);
            float q1b = __shfl_sync(0xffffffffu, p3, s0, 4);
            float q2a = __shfl_sync(0xffffffffu, p0, s0 + 2, 4);
            float q2b = __shfl_sync(0xffffffffu, p1, s0 + 2, 4);
            float q3a = __shfl_sync(0xffffffffu, p2, s0 + 2, 4);
            float q3b = __shfl_sync(0xffffffffu, p3, s0 + 2, 4);
            unsigned a[4];
            a[0] = f2tf32(odd ? q0b : q0a);
            a[1] = f2tf32(odd ? q1b : q1a);
            a[2] = f2tf32(odd ? q2b : q2a);
            a[3] = f2tf32(odd ? q3b : q3a);

            int k0 = ks * 8;
            #pragma unroll
            for (int nt = 0; nt < 16; nt++) {
                const unsigned* bp = &bufV[(k0 + tig) * FV_STR + nt*8 + gid];
                mma_tf32(acc_o[nt], a, bp[0], bp[4*FV_STR]);
            }
        }

        if (j + 1 < FL_NT) {
            __syncthreads();
            cp_tile(FL_QW + FL_KW, Vbase + (long)(j+1)*128 * ld, FV_STR);
            cp_commit();
        }
    }

    float inv0 = 1.f / l0, inv1 = 1.f / l1;
    long rbase = (baserow + qt*128 + warp*16 + gid) * HSZ + hc;
    #pragma unroll
    for (int nt = 0; nt < 16; nt++) {
        int c0 = nt*8 + tig*2;
        float2 x0 = *(const float2*)(X + rbase + c0);
        float2 x1 = *(const float2*)(X + rbase + 8*HSZ + c0);
        float2 o0 = make_float2(acc_o[nt][0]*inv0 + x0.x, acc_o[nt][1]*inv0 + x0.y);
        float2 o1 = make_float2(acc_o[nt][2]*inv1 + x1.x, acc_o[nt][3]*inv1 + x1.y);
        *(float2*)(O + rbase + c0)           = o0;
        *(float2*)(O + rbase + 8*HSZ + c0)   = o1;
    }
}

// ---------------- tf32 GEMM v3: cp.async double-buffer, pre-rounded inputs ----------------
// C[m][n] = sum_k A[m][k] * B[k][n]  (+bias)(prelu)(+res)(tf32-rounded store if RNDOUT).
// 128x128 tile, k-chunk 32, 8 warps 4x2, warp tile 32x64.
// As stride 36 (bank 4*gid+tig distinct), Bs stride 136 (bank 8*tig+gid distinct).
#define GA_STR 36
#define GB_STR 136
#define G_AW   (128 * GA_STR)
#define G_BW   (32 * GB_STR)
#define G_STG  (G_AW + G_BW)
#define G_BYTES (2 * G_STG * 4)

template<bool RNDOUT>
__global__ void __launch_bounds__(256, 2) gemm_mma(
    const float* __restrict__ A, const float* __restrict__ B, float* __restrict__ C,
    int N, int K, int lda, int ldb, int ldc,
    const float* __restrict__ bias,
    const float* __restrict__ prelu,
    const float* __restrict__ res)
{
    extern __shared__ unsigned gsm[];
    unsigned sbase = (unsigned)__cvta_generic_to_shared(gsm);

    int bm = blockIdx.y << 7;
    int bn = blockIdx.x << 7;

    int tid  = threadIdx.x;
    int warp = tid >> 5, lane = tid & 31;
    int wm = warp >> 1, wn = warp & 1;
    int gid = lane >> 2, tig = lane & 3;

    auto load_chunk = [&](int stage, int c) {
        unsigned aw = sbase + (stage * G_STG) * 4;
        const float* pa = A + (long)bm * lda + c * 32;
        #pragma unroll
        for (int t = 0; t < 4; t++) {
            int i = tid + t * 256;               // 0..1023 float4s of A chunk
            int r = i >> 3, c4 = (i & 7) << 2;
            cp16(aw + (r * GA_STR + c4) * 4, pa + (long)r * lda + c4);
        }
        unsigned bw = sbase + (stage * G_STG + G_AW) * 4;
        const float* pb = B + (long)(c * 32) * ldb + bn;
        #pragma unroll
        for (int t = 0; t < 4; t++) {
            int i = tid + t * 256;               // 0..1023 float4s of B chunk
            int k = i >> 5, c4 = (i & 31) << 2;
            cp16(bw + (k * GB_STR + c4) * 4, pb + (long)k * ldb + c4);
        }
        cp_commit();
    };

    float acc[2][8][4];
    #pragma unroll
    for (int mt = 0; mt < 2; mt++)
        #pragma unroll
        for (int nt = 0; nt < 8; nt++)
            #pragma unroll
            for (int i = 0; i < 4; i++) acc[mt][nt][i] = 0.f;

    const int nch = K >> 5;
    load_chunk(0, 0);

    for (int c = 0; c < nch; c++) {
        int cur = c & 1;
        if (c + 1 < nch) {
            load_chunk(cur ^ 1, c + 1);
            asm volatile("cp.async.wait_group 1;" ::: "memory");
        } else {
            asm volatile("cp.async.wait_group 0;" ::: "memory");
        }
        __syncthreads();

        const unsigned* As = gsm + cur * G_STG;
        const unsigned* Bs = As + G_AW;

        #pragma unroll
        for (int ks = 0; ks < 4; ks++) {
            int kk = ks * 8 + tig;
            unsigned a[2][4];
            #pragma unroll
            for (int mt = 0; mt < 2; mt++) {
                const unsigned* ap = &As[(wm * 32 + mt * 16 + gid) * GA_STR + kk];
                a[mt][0] = ap[0];
                a[mt][1] = ap[8 * GA_STR];
                a[mt][2] = ap[4];
                a[mt][3] = ap[8 * GA_STR + 4];
            }
            #pragma unroll
            for (int nt = 0; nt < 8; nt++) {
                int ncol = wn * 64 + nt * 8 + gid;
                const unsigned* bp = &Bs[kk * GB_STR + ncol];
                unsigned b0 = bp[0], b1 = bp[4 * GB_STR];
                mma_tf32(acc[0][nt], a[0], b0, b1);
                mma_tf32(acc[1][nt], a[1], b0, b1);
            }
        }
        __syncthreads();
    }

    // ---- epilogue ----
    #pragma unroll
    for (int mt = 0; mt < 2; mt++) {
        int r0 = bm + wm * 32 + mt * 16 + gid;
        #pragma unroll
        for (int nt = 0; nt < 8; nt++) {
            int c0 = bn + wn * 64 + nt * 8 + tig * 2;
            float v0 = acc[mt][nt][0];
            float v1 = acc[mt][nt][1];
            float v2 = acc[mt][nt][2];
            float v3 = acc[mt][nt][3];
            if (bias) {
                float b0v = bias[c0], b1v = bias[c0 + 1];
                v0 += b0v; v1 += b1v; v2 += b0v; v3 += b1v;
            }
            if (prelu) {
                float p0 = prelu[c0], p1 = prelu[c0 + 1];
                v0 = v0 > 0.f ? v0 : v0 * p0;
                v1 = v1 > 0.f ? v1 : v1 * p1;
                v2 = v2 > 0.f ? v2 : v2 * p0;
                v3 = v3 > 0.f ? v3 : v3 * p1;
            }
            if (res) {
                float2 q0 = *(const float2*)(res + (long)r0 * ldc + c0);
                float2 q1 = *(const float2*)(res + (long)(r0 + 8) * ldc + c0);
                v0 += q0.x; v1 += q0.y; v2 += q1.x; v3 += q1.y;
            }
            if (RNDOUT) {
                v0 = f2tf32f(v0); v1 = f2tf32f(v1);
                v2 = f2tf32f(v2); v3 = f2tf32f(v3);
            }
            *(float2*)(C + (long)r0 * ldc + c0)       = make_float2(v0, v1);
            *(float2*)(C + (long)(r0 + 8) * ldc + c0) = make_float2(v2, v3);
        }
    }
}

// ---------------- layer norm over rows of 512 (optional tf32-rounded store) ----------------
template<bool RNDOUT>
__global__ void __launch_bounds__(128) layernorm_kernel(
    const float* __restrict__ in, float* __restrict__ out,
    const float* __restrict__ gamma, const float* __restrict__ beta)
{
    long row = blockIdx.x;
    int tid = threadIdx.x, lane = tid & 31, wid = tid >> 5;
    float4 v = ((const float4*)(in + row * HSZ))[tid];

    __shared__ float red[8];
    float s = v.x + v.y + v.z + v.w;
    #pragma unroll
    for (int o = 16; o > 0; o >>= 1) s += __shfl_xor_sync(0xffffffffu, s, o);
    if (lane == 0) red[wid] = s;
    __syncthreads();
    float mu = (red[0] + red[1] + red[2] + red[3]) * (1.f / HSZ);

    float dx = v.x - mu, dy = v.y - mu, dz = v.z - mu, dw = v.w - mu;
    float q = dx*dx + dy*dy + dz*dz + dw*dw;
    #pragma unroll
    for (int o = 16; o > 0; o >>= 1) q += __shfl_xor_sync(0xffffffffu, q, o);
    if (lane == 0) red[4 + wid] = q;
    __syncthreads();
    float var = (red[4] + red[5] + red[6] + red[7]) * (1.f / HSZ);
    float rstd = rsqrtf(var + 1e-5f);

    float4 g = ((const float4*)gamma)[tid];
    float4 bb = ((const float4*)beta)[tid];
    float4 o4;
    o4.x = dx * rstd * g.x + bb.x;
    o4.y = dy * rstd * g.y + bb.y;
    o4.z = dz * rstd * g.z + bb.z;
    o4.w = dw * rstd * g.w + bb.w;
    if (RNDOUT) {
        o4.x = f2tf32f(o4.x); o4.y = f2tf32f(o4.y);
        o4.z = f2tf32f(o4.z); o4.w = f2tf32f(o4.w);
    }
    ((float4*)(out + row * HSZ))[tid] = o4;
}

// ---------------- output assembly: [glob | nodes | mask] ----------------
__global__ void __launch_bounds__(256) write_out_kernel(float* __restrict__ out, long out_size)
{
    long i = (long)blockIdx.x * 256 + threadIdx.x;
    if (i >= out_size) return;
    const long G  = (long)BB * HSZ;                 // 8192
    const long ND = (long)BB * NN * HSZ;            // 8388608
    if (i < G) {
        long b = i >> 9;
        long c = i & 511;
        out[i] = g_x[(b * NN + EE) * HSZ + c];
    } else if (i < G + ND) {
        out[i] = g_x[i - G];
    } else {
        out[i] = 1.0f;
    }
}

// ---------------- orchestration ----------------
extern "C" void kernel_launch(void* const* d_in, const int* in_sizes, int n_in,
                              void* d_out, int out_size)
{
    const float* ents = (const float*)d_in[0];
    const int*   rels = (const int*)  d_in[1];
    const int*   adj  = (const int*)  d_in[2];
    const float* renc = (const float*)d_in[3];
    const float* Wq   = (const float*)d_in[4];
    const float* Wk   = (const float*)d_in[5];
    const float* Wv   = (const float*)d_in[6];
    const float* l1w  = (const float*)d_in[7];
    const float* l1b  = (const float*)d_in[8];
    const float* l2w  = (const float*)d_in[9];
    const float* l2b  = (const float*)d_in[10];
    const float* ln1s = (const float*)d_in[11];
    const float* ln1b = (const float*)d_in[12];
    const float* ln2s = (const float*)d_in[13];
    const float* ln2b = (const float*)d_in[14];
    const float* pa   = (const float*)d_in[15];

    float *gx, *go, *gt, *gh, *gw, *gw1, *gw2;
    cudaGetSymbolAddress((void**)&gx, g_x);
    cudaGetSymbolAddress((void**)&go, g_o);
    cudaGetSymbolAddress((void**)&gt, g_t);
    cudaGetSymbolAddress((void**)&gh, g_h);
    cudaGetSymbolAddress((void**)&gw, g_w);
    cudaGetSymbolAddress((void**)&gw1, g_w1);
    cudaGetSymbolAddress((void**)&gw2, g_w2);

    cudaFuncSetAttribute(flash_kernel, cudaFuncAttributeMaxDynamicSharedMemorySize, FL_BYTES);
    cudaFuncSetAttribute(gemm_mma<false>, cudaFuncAttributeMaxDynamicSharedMemorySize, G_BYTES);
    cudaFuncSetAttribute(gemm_mma<true>,  cudaFuncAttributeMaxDynamicSharedMemorySize, G_BYTES);

    const long M = (long)BB * NN;                   // 16384

    // gather x (tf32-rounded)
    {
        long tot = M * (HSZ/4);
        gather_kernel<<<(unsigned)((tot + 255) / 256), 256>>>(ents, rels, renc);
    }
    // adj -> bitmask (once)
    {
        long tot = (long)BB * NN * (NN/32);
        mask_kernel<<<(unsigned)((tot + 255) / 256), 256>>>(adj);
    }
    // pack + round weights (once)
    {
        long tot = (long)PROP * HSZ * (NQKV/4);
        pack_w_kernel<<<(unsigned)((tot + 255) / 256), 256>>>(Wq, Wk, Wv);
        long tot2 = (long)PROP * HSZ * DFF / 4;
        pack_ffn_kernel<<<(unsigned)((tot2 + 255) / 256), 256>>>(l1w, l2w);
    }

    for (int j = 0; j < PROP; j++) {
        // [Q|K|V] = x @ g_w  -> g_h as [M][1536] (raw fp32; flash converts)
        gemm_mma<false><<<dim3(NQKV/128, (unsigned)(M/128)), 256, G_BYTES>>>(
            gx, gw + (long)j*HSZ*NQKV, gh, NQKV, HSZ, HSZ, NQKV, NQKV,
            nullptr, nullptr, nullptr);

        // fused attention + residual -> g_o
        flash_kernel<<<dim3(NN/128, HEADS, BB), 256, FL_BYTES>>>(gh, NQKV, gx, go);

        // t = LN1(out), rounded (FFN1 input + FFN2 residual)
        layernorm_kernel<true><<<(unsigned)M, 128>>>(go, gt, ln1s + j*HSZ, ln1b + j*HSZ);

        // h = prelu(t @ l1_w + l1_b), rounded store (FFN2 input)
        gemm_mma<true><<<dim3(DFF/128, (unsigned)(M/128)), 256, G_BYTES>>>(
            gt, gw1 + (long)j*HSZ*DFF, gh, DFF, HSZ, HSZ, DFF, DFF,
            l1b + (long)j*DFF, pa + (long)j*DFF, nullptr);

        // o = h @ l2_w + l2_b + t (raw store; feeds LN only)
        gemm_mma<false><<<dim3(HSZ/128, (unsigned)(M/128)), 256, G_BYTES>>>(
            gh, gw2 + (long)j*DFF*HSZ, go, HSZ, DFF, DFF, HSZ, HSZ,
            l2b + (long)j*HSZ, nullptr, gt);

        // x = LN2(o): rounded for inner layers (next QKV input), raw for final output
        if (j < PROP - 1)
            layernorm_kernel<true><<<(unsigned)M, 128>>>(go, gx, ln2s + j*HSZ, ln2b + j*HSZ);
        else
            layernorm_kernel<false><<<(unsigned)M, 128>>>(go, gx, ln2s + j*HSZ, ln2b + j*HSZ);
    }

    // assemble output
    {
        long os = (long)out_size;
        write_out_kernel<<<(unsigned)((os + 255) / 256), 256>>>((float*)d_out, os);
    }
}

// round 12
// speedup vs baseline: 1.6394x; 1.1171x over previous
#include <cuda_runtime.h>
#include <cuda_fp16.h>
#include <float.h>
#include <math.h>

// ---------------- problem constants ----------------
#define BB   16
#define EE   400
#define RR   624
#define NN   1024
#define HSZ  512
#define HEADS 4
#define DK   128
#define DFF  2048
#define PROP 2
#define RTOKS 40
#define NQKV 1536
#define MTOT ((long)BB*NN)

// ---------------- scratch (device globals) ----------------
__device__ float  g_x[(long)BB*NN*HSZ];            // fp32 residual / final out
__device__ float  g_o[(long)BB*NN*HSZ];            // fp32 pre-LN
__device__ __half g_xh[(long)BB*NN*HSZ];           // fp16 activation (QKV A)
__device__ __half g_t16[(long)BB*NN*HSZ];          // fp16 LN1 out (FFN1 A, FFN2 res)
__device__ __half g_h16[(long)BB*NN*DFF];          // fp16 QKV out / FFN1 out
__device__ __half g_vt[(long)BB*HEADS*DK*NN];      // fp16 transposed V
__device__ __half g_w16[(long)PROP*NQKV*HSZ];      // [n][k] packed QKV weights (Wq pre-scaled)
__device__ __half g_w1t[(long)PROP*DFF*HSZ];       // [n][k] l1_w
__device__ __half g_w2t[(long)PROP*HSZ*DFF];       // [n][k] l2_w
__device__ unsigned g_mask[(long)BB*NN*(NN/32)];

// ---------------- helpers ----------------
__device__ __forceinline__ void mma_f16(float* c, const unsigned* a, unsigned b0, unsigned b1) {
    asm volatile(
        "mma.sync.aligned.m16n8k16.row.col.f32.f16.f16.f32 "
        "{%0,%1,%2,%3}, {%4,%5,%6,%7}, {%8,%9}, {%0,%1,%2,%3};\n"
        : "+f"(c[0]), "+f"(c[1]), "+f"(c[2]), "+f"(c[3])
        : "r"(a[0]), "r"(a[1]), "r"(a[2]), "r"(a[3]), "r"(b0), "r"(b1));
}
__device__ __forceinline__ unsigned f22h(float lo, float hi) {
    __half2 h = __floats2half2_rn(lo, hi);
    return *(unsigned*)&h;
}
__device__ __forceinline__ void cp16(unsigned dst, const void* src) {
    asm volatile("cp.async.cg.shared.global [%0], [%1], 16;" :: "r"(dst), "l"(src) : "memory");
}
__device__ __forceinline__ void cp_commit() {
    asm volatile("cp.async.commit_group;" ::: "memory");
}

// ---------------- gather: x = concat(ents, renc[rels]) -> fp32 + fp16 ----------------
__global__ void __launch_bounds__(256) gather_kernel(
    const float* __restrict__ ents, const int* __restrict__ rels,
    const float* __restrict__ renc)
{
    long i = (long)blockIdx.x * 256 + threadIdx.x;          // float4 index
    const long TOT = MTOT * (HSZ / 4);
    if (i >= TOT) return;
    int c  = (int)(i & (HSZ/4 - 1));
    long bn = i >> 7;
    int n  = (int)(bn & (NN - 1));
    int b  = (int)(bn >> 10);
    float4 v;
    if (n < EE) {
        v = ((const float4*)ents)[((long)b*EE + n)*(HSZ/4) + c];
    } else {
        int r = rels[b*RR + (n - EE)];
        v = ((const float4*)renc)[(long)r*(HSZ/4) + c];
    }
    ((float4*)g_x)[i] = v;
    uint2 h = make_uint2(f22h(v.x, v.y), f22h(v.z, v.w));
    ((uint2*)g_xh)[i] = h;
}

// ---------------- adj -> bitmask ----------------
__global__ void __launch_bounds__(256) mask_kernel(const int* __restrict__ adj)
{
    long i = (long)blockIdx.x * 256 + threadIdx.x;
    const long TOT = (long)BB * NN * (NN / 32);
    if (i >= TOT) return;
    const int* p = adj + i * 32;
    unsigned m = 0;
    #pragma unroll
    for (int t = 0; t < 8; t++) {
        int4 a = ((const int4*)p)[t];
        m |= (a.x ? 1u : 0u) << (t*4 + 0);
        m |= (a.y ? 1u : 0u) << (t*4 + 1);
        m |= (a.z ? 1u : 0u) << (t*4 + 2);
        m |= (a.w ? 1u : 0u) << (t*4 + 3);
    }
    g_mask[i] = m;
}

// ---------------- pack weights: [k][n] fp32 -> [n][k] fp16 ----------------
__global__ void __launch_bounds__(256) pack_w_kernel(
    const float* __restrict__ Wq, const float* __restrict__ Wk,
    const float* __restrict__ Wv)
{
    const float scale = 0.04419417382415922f;  // 1/sqrt(512), folded into Wq
    long i = (long)blockIdx.x * 256 + threadIdx.x;          // output half index
    const long TOT = (long)PROP * NQKV * HSZ;
    if (i >= TOT) return;
    int k = (int)(i & (HSZ - 1));
    long jn = i >> 9;
    int n = (int)(jn % NQKV);
    int j = (int)(jn / NQKV);
    float v;
    if (n < 512)       v = Wq[((long)j*512 + k)*512 + n] * scale;
    else if (n < 1024) v = Wk[((long)j*512 + k)*512 + (n - 512)];
    else               v = Wv[((long)j*512 + k)*512 + (n - 1024)];
    g_w16[i] = __float2half_rn(v);
}

__global__ void __launch_bounds__(256) pack_ffn_kernel(
    const float* __restrict__ l1w, const float* __restrict__ l2w)
{
    long i = (long)blockIdx.x * 256 + threadIdx.x;
    const long T1 = (long)PROP * DFF * HSZ;                 // g_w1t halves
    if (i < T1) {
        int k = (int)(i & (HSZ - 1));                       // 0..511
        long jn = i >> 9;
        int n = (int)(jn % DFF);
        int j = (int)(jn / DFF);
        g_w1t[i] = __float2half_rn(l1w[((long)j*512 + k)*DFF + n]);
    }
    if (i < (long)PROP * HSZ * DFF) {                       // g_w2t halves
        int k = (int)(i & (DFF - 1));                       // 0..2047
        long jn = i >> 11;
        int n = (int)(jn % HSZ);
        int j = (int)(jn / HSZ);
        g_w2t[i] = __float2half_rn(l2w[((long)j*DFF + k)*HSZ + n]);
    }
}

// ---------------- V transpose: qkv[M][1536] V-part -> vt[b][h][dk][NN] ----------------
__global__ void __launch_bounds__(256) vtrans_kernel(const __half* __restrict__ qkv)
{
    __shared__ __half st[64][72];
    int stile = blockIdx.x;                 // 0..15 (s block of 64)
    int hd = blockIdx.y;                    // h*2 + dtile
    int b = blockIdx.z;
    int h = hd >> 1, dt = hd & 1;
    int s0 = stile * 64, d0 = dt * 64;
    int tid = threadIdx.x;

    // load 64 s-rows x 64 d-cols (half2 coalesced)
    #pragma unroll
    for (int t = 0; t < 8; t++) {
        int idx = tid + t * 256;
        int r = idx >> 5, c2 = idx & 31;
        const __half* src = qkv + ((long)(b*NN + s0 + r)) * NQKV + 1024 + h*DK + d0 + 2*c2;
        *(__half2*)&st[r][2*c2] = *(const __half2*)src;
    }
    __syncthreads();
    // write 64 d-rows x 64 s-cols (half2 coalesced along s)
    #pragma unroll
    for (int t = 0; t < 8; t++) {
        int idx = tid + t * 256;
        int d = idx >> 5, s2 = idx & 31;
        __half2 o;
        o.x = st[2*s2][d];
        o.y = st[2*s2 + 1][d];
        __half* dst = g_vt + ((long)((b*HEADS + h)*DK + d0 + d)) * NN + s0 + 2*s2;
        *(__half2*)dst = o;
    }
}

// ---------------- fused flash attention fp16 ----------------
// sQ/bufK: [row][k2] stride 68 words; bufV: [dk][s-k2] stride 68 words.
#define FL_STR 68
#define FL_W   (128 * FL_STR)
#define FL_BYTES (3 * FL_W * 4)
#define FL_NT  (NN / 128)

__global__ void __launch_bounds__(256) flash_kernel(
    const __half* __restrict__ QKV, const __half* __restrict__ VT,
    const float* __restrict__ X, float* __restrict__ O)
{
    extern __shared__ unsigned sm[];
    unsigned* sQ   = sm;
    unsigned* bufK = sm + FL_W;
    unsigned* bufV = sm + 2 * FL_W;
    unsigned sbase = (unsigned)__cvta_generic_to_shared(sm);

    int qt = blockIdx.x, h = blockIdx.y, b = blockIdx.z;
    int tid = threadIdx.x, warp = tid >> 5, lane = tid & 31;
    int gid = lane >> 2, tig = lane & 3;

    const long baserow = (long)b * NN;
    const __half* Qsrc  = QKV + (baserow + qt*128) * NQKV + h*DK;
    const __half* Kbase = QKV + baserow * NQKV + 512 + h*DK;
    const __half* Vbase = VT + ((long)(b*HEADS + h)) * DK * NN;

    // cp a 128x128-half tile; src rows stride srcld halves
    auto cp_tile = [&](unsigned dstW, const __half* src, int srcld) {
        #pragma unroll
        for (int t = 0; t < 8; t++) {
            int i = tid + t * 256;
            int r = i >> 4, c = i & 15;
            cp16(sbase + (dstW + r * FL_STR + c * 4) * 4, src + (long)r * srcld + c * 8);
        }
    };

    cp_tile(0, Qsrc, NQKV);           cp_commit();
    cp_tile(FL_W, Kbase, NQKV);       cp_commit();
    cp_tile(2*FL_W, Vbase, NN);       cp_commit();

    float acc_o[16][4];
    #pragma unroll
    for (int nt = 0; nt < 16; nt++)
        #pragma unroll
        for (int i = 0; i < 4; i++) acc_o[nt][i] = 0.f;

    float m0 = -INFINITY, m1 = -INFINITY, l0 = 0.f, l1 = 0.f;
    const unsigned* mrow0 = g_mask + ((long)b*NN + qt*128 + warp*16 + gid) * (NN/32);
    const unsigned* mrow1 = mrow0 + 8 * (NN/32);

    float acc_s[16][4];

    for (int j = 0; j < FL_NT; j++) {
        asm volatile("cp.async.wait_group 1;" ::: "memory");   // K_j ready
        __syncthreads();

        #pragma unroll
        for (int nt = 0; nt < 16; nt++)
            #pragma unroll
            for (int i = 0; i < 4; i++) acc_s[nt][i] = 0.f;

        // S = Q @ K^T : 8 k16 steps over dk=128
        #pragma unroll
        for (int ks = 0; ks < 8; ks++) {
            const unsigned* ap = &sQ[(warp*16 + gid) * FL_STR + ks*8 + tig];
            unsigned a[4];
            a[0] = ap[0]; a[1] = ap[8*FL_STR]; a[2] = ap[4]; a[3] = ap[8*FL_STR + 4];
            #pragma unroll
            for (int nt = 0; nt < 16; nt++) {
                const unsigned* bp = &bufK[(nt*8 + gid) * FL_STR + ks*8 + tig];
                mma_f16(acc_s[nt], a, bp[0], bp[4]);
            }
        }

        __syncthreads();
        if (j + 1 < FL_NT) {
            cp_tile(FL_W, Kbase + (long)(j+1)*128 * NQKV, NQKV);
            cp_commit();
        }

        // mask + online softmax
        unsigned mw0[4], mw1[4];
        #pragma unroll
        for (int w = 0; w < 4; w++) { mw0[w] = mrow0[j*4 + w]; mw1[w] = mrow1[j*4 + w]; }

        float tm0 = -INFINITY, tm1 = -INFINITY;
        #pragma unroll
        for (int nt = 0; nt < 16; nt++) {
            int c0 = nt*8 + tig*2;
            unsigned w = nt >> 2;
            int bi = c0 & 31;
            acc_s[nt][0] = ((mw0[w] >> bi)     & 1) ? acc_s[nt][0] : -1e30f;
            acc_s[nt][1] = ((mw0[w] >> (bi+1)) & 1) ? acc_s[nt][1] : -1e30f;
            acc_s[nt][2] = ((mw1[w] >> bi)     & 1) ? acc_s[nt][2] : -1e30f;
            acc_s[nt][3] = ((mw1[w] >> (bi+1)) & 1) ? acc_s[nt][3] : -1e30f;
            tm0 = fmaxf(tm0, fmaxf(acc_s[nt][0], acc_s[nt][1]));
            tm1 = fmaxf(tm1, fmaxf(acc_s[nt][2], acc_s[nt][3]));
        }
        tm0 = fmaxf(tm0, __shfl_xor_sync(0xffffffffu, tm0, 1));
        tm0 = fmaxf(tm0, __shfl_xor_sync(0xffffffffu, tm0, 2));
        tm1 = fmaxf(tm1, __shfl_xor_sync(0xffffffffu, tm1, 1));
        tm1 = fmaxf(tm1, __shfl_xor_sync(0xffffffffu, tm1, 2));

        float nm0 = fmaxf(m0, tm0), nm1 = fmaxf(m1, tm1);
        float f0 = __expf(m0 - nm0), f1 = __expf(m1 - nm1);

        float sum0 = 0.f, sum1 = 0.f;
        #pragma unroll
        for (int nt = 0; nt < 16; nt++) {
            float p0 = __expf(acc_s[nt][0] - nm0);
            float p1 = __expf(acc_s[nt][1] - nm0);
            float p2 = __expf(acc_s[nt][2] - nm1);
            float p3 = __expf(acc_s[nt][3] - nm1);
            sum0 += p0 + p1; sum1 += p2 + p3;
            acc_s[nt][0] = p0; acc_s[nt][1] = p1;
            acc_s[nt][2] = p2; acc_s[nt][3] = p3;
        }
        sum0 += __shfl_xor_sync(0xffffffffu, sum0, 1);
        sum0 += __shfl_xor_sync(0xffffffffu, sum0, 2);
        sum1 += __shfl_xor_sync(0xffffffffu, sum1, 1);
        sum1 += __shfl_xor_sync(0xffffffffu, sum1, 2);

        l0 = l0 * f0 + sum0;  l1 = l1 * f1 + sum1;
        m0 = nm0;  m1 = nm1;
        #pragma unroll
        for (int nt = 0; nt < 16; nt++) {
            acc_o[nt][0] *= f0; acc_o[nt][1] *= f0;
            acc_o[nt][2] *= f1; acc_o[nt][3] *= f1;
        }

        if (j + 1 < FL_NT) asm volatile("cp.async.wait_group 1;" ::: "memory");
        else               asm volatile("cp.async.wait_group 0;" ::: "memory");
        __syncthreads();

        // O += P @ V : P acc-layout == fp16 A-frag layout (no shuffles!)
        #pragma unroll
        for (int ks = 0; ks < 8; ks++) {
            unsigned a[4];
            a[0] = f22h(acc_s[2*ks][0],   acc_s[2*ks][1]);
            a[1] = f22h(acc_s[2*ks][2],   acc_s[2*ks][3]);
            a[2] = f22h(acc_s[2*ks+1][0], acc_s[2*ks+1][1]);
            a[3] = f22h(acc_s[2*ks+1][2], acc_s[2*ks+1][3]);
            #pragma unroll
            for (int nt = 0; nt < 16; nt++) {
                const unsigned* bp = &bufV[(nt*8 + gid) * FL_STR + ks*8 + tig];
                mma_f16(acc_o[nt], a, bp[0], bp[4]);
            }
        }

        if (j + 1 < FL_NT) {
            __syncthreads();
            cp_tile(2*FL_W, Vbase + (j+1)*128, NN);
            cp_commit();
        }
    }

    float inv0 = 1.f / l0, inv1 = 1.f / l1;
    long rbase = (baserow + qt*128 + warp*16 + gid) * HSZ + h*DK;
    #pragma unroll
    for (int nt = 0; nt < 16; nt++) {
        int c0 = nt*8 + tig*2;
        float2 x0 = *(const float2*)(X + rbase + c0);
        float2 x1 = *(const float2*)(X + rbase + 8*HSZ + c0);
        float2 o0 = make_float2(acc_o[nt][0]*inv0 + x0.x, acc_o[nt][1]*inv0 + x0.y);
        float2 o1 = make_float2(acc_o[nt][2]*inv1 + x1.x, acc_o[nt][3]*inv1 + x1.y);
        *(float2*)(O + rbase + c0)         = o0;
        *(float2*)(O + rbase + 8*HSZ + c0) = o1;
    }
}

// ---------------- fp16 GEMM: C[m][n] = A[m][k] @ B[n][k]^T, k-chunk 64 ----------------
// A smem [row][k2] str 36; B smem [n][k2] str 36 (both frag banks 4*gid+tig distinct).
#define GSTR 36
#define G_AW (128 * GSTR)
#define G_STG (2 * G_AW)
#define G_BYTES (2 * G_STG * 4)

template<bool OUT16>
__global__ void __launch_bounds__(256, 2) gemm16(
    const __half* __restrict__ A, const __half* __restrict__ B, void* __restrict__ Cv,
    int K, int lda, int ldb, int ldc,
    const float* __restrict__ bias,
    const float* __restrict__ prelu,
    const __half* __restrict__ res)
{
    extern __shared__ unsigned gsm[];
    unsigned sbase = (unsigned)__cvta_generic_to_shared(gsm);

    int bm = blockIdx.y << 7;
    int bn = blockIdx.x << 7;

    int tid  = threadIdx.x;
    int warp = tid >> 5, lane = tid & 31;
    int wm = warp >> 1, wn = warp & 1;
    int gid = lane >> 2, tig = lane & 3;

    auto load_chunk = [&](int stage, int c) {
        unsigned aw = sbase + (stage * G_STG) * 4;
        const __half* pa = A + (long)bm * lda + c * 64;
        #pragma unroll
        for (int t = 0; t < 4; t++) {
            int i = tid + t * 256;
            int r = i >> 3, cc = i & 7;
            cp16(aw + (r * GSTR + cc * 4) * 4, pa + (long)r * lda + cc * 8);
        }
        unsigned bw = sbase + (stage * G_STG + G_AW) * 4;
        const __half* pb = B + (long)bn * ldb + c * 64;
        #pragma unroll
        for (int t = 0; t < 4; t++) {
            int i = tid + t * 256;
            int r = i >> 3, cc = i & 7;
            cp16(bw + (r * GSTR + cc * 4) * 4, pb + (long)r * ldb + cc * 8);
        }
        cp_commit();
    };

    float acc[2][8][4];
    #pragma unroll
    for (int mt = 0; mt < 2; mt++)
        #pragma unroll
        for (int nt = 0; nt < 8; nt++)
            #pragma unroll
            for (int i = 0; i < 4; i++) acc[mt][nt][i] = 0.f;

    const int nch = K >> 6;
    load_chunk(0, 0);

    for (int c = 0; c < nch; c++) {
        int cur = c & 1;
        if (c + 1 < nch) {
            load_chunk(cur ^ 1, c + 1);
            asm volatile("cp.async.wait_group 1;" ::: "memory");
        } else {
            asm volatile("cp.async.wait_group 0;" ::: "memory");
        }
        __syncthreads();

        const unsigned* As = gsm + cur * G_STG;
        const unsigned* Bs = As + G_AW;

        #pragma unroll
        for (int ks = 0; ks < 4; ks++) {
            unsigned a[2][4];
            #pragma unroll
            for (int mt = 0; mt < 2; mt++) {
                const unsigned* ap = &As[(wm*32 + mt*16 + gid) * GSTR + ks*8 + tig];
                a[mt][0] = ap[0];
                a[mt][1] = ap[8 * GSTR];
                a[mt][2] = ap[4];
                a[mt][3] = ap[8 * GSTR + 4];
            }
            #pragma unroll
            for (int nt = 0; nt < 8; nt++) {
                const unsigned* bp = &Bs[(wn*64 + nt*8 + gid) * GSTR + ks*8 + tig];
                unsigned b0 = bp[0], b1 = bp[4];
                mma_f16(acc[0][nt], a[0], b0, b1);
                mma_f16(acc[1][nt], a[1], b0, b1);
            }
        }
        __syncthreads();
    }

    // epilogue
    #pragma unroll
    for (int mt = 0; mt < 2; mt++) {
        int r0 = bm + wm * 32 + mt * 16 + gid;
        #pragma unroll
        for (int nt = 0; nt < 8; nt++) {
            int c0 = bn + wn * 64 + nt * 8 + tig * 2;
            float v0 = acc[mt][nt][0];
            float v1 = acc[mt][nt][1];
            float v2 = acc[mt][nt][2];
            float v3 = acc[mt][nt][3];
            if (bias) {
                float b0v = bias[c0], b1v = bias[c0 + 1];
                v0 += b0v; v1 += b1v; v2 += b0v; v3 += b1v;
            }
            if (prelu) {
                float p0 = prelu[c0], p1 = prelu[c0 + 1];
                v0 = v0 > 0.f ? v0 : v0 * p0;
                v1 = v1 > 0.f ? v1 : v1 * p1;
                v2 = v2 > 0.f ? v2 : v2 * p0;
                v3 = v3 > 0.f ? v3 : v3 * p1;
            }
            if (res) {
                __half2 q0 = *(const __half2*)(res + (long)r0 * ldc + c0);
                __half2 q1 = *(const __half2*)(res + (long)(r0 + 8) * ldc + c0);
                v0 += __half2float(q0.x); v1 += __half2float(q0.y);
                v2 += __half2float(q1.x); v3 += __half2float(q1.y);
            }
            if (OUT16) {
                __half* C = (__half*)Cv;
                *(unsigned*)(C + (long)r0 * ldc + c0)       = f22h(v0, v1);
                *(unsigned*)(C + (long)(r0 + 8) * ldc + c0) = f22h(v2, v3);
            } else {
                float* C = (float*)Cv;
                *(float2*)(C + (long)r0 * ldc + c0)       = make_float2(v0, v1);
                *(float2*)(C + (long)(r0 + 8) * ldc + c0) = make_float2(v2, v3);
            }
        }
    }
}

// ---------------- layer norm: fp32 in; MODE 0=fp32 only, 1=fp16 only, 2=both ----------------
template<int MODE>
__global__ void __launch_bounds__(128) layernorm_kernel(
    const float* __restrict__ in, float* __restrict__ out32, __half* __restrict__ out16,
    const float* __restrict__ gamma, const float* __restrict__ beta)
{
    long row = blockIdx.x;
    int tid = threadIdx.x, lane = tid & 31, wid = tid >> 5;
    float4 v = ((const float4*)(in + row * HSZ))[tid];

    __shared__ float red[8];
    float s = v.x + v.y + v.z + v.w;
    #pragma unroll
    for (int o = 16; o > 0; o >>= 1) s += __shfl_xor_sync(0xffffffffu, s, o);
    if (lane == 0) red[wid] = s;
    __syncthreads();
    float mu = (red[0] + red[1] + red[2] + red[3]) * (1.f / HSZ);

    float dx = v.x - mu, dy = v.y - mu, dz = v.z - mu, dw = v.w - mu;
    float q = dx*dx + dy*dy + dz*dz + dw*dw;
    #pragma unroll
    for (int o = 16; o > 0; o >>= 1) q += __shfl_xor_sync(0xffffffffu, q, o);
    if (lane == 0) red[4 + wid] = q;
    __syncthreads();
    float var = (red[4] + red[5] + red[6] + red[7]) * (1.f / HSZ);
    float rstd = rsqrtf(var + 1e-5f);

    float4 g = ((const float4*)gamma)[tid];
    float4 bb = ((const float4*)beta)[tid];
    float4 o4;
    o4.x = dx * rstd * g.x + bb.x;
    o4.y = dy * rstd * g.y + bb.y;
    o4.z = dz * rstd * g.z + bb.z;
    o4.w = dw * rstd * g.w + bb.w;
    if (MODE != 1) ((float4*)(out32 + row * HSZ))[tid] = o4;
    if (MODE != 0) {
        uint2 h = make_uint2(f22h(o4.x, o4.y), f22h(o4.z, o4.w));
        ((uint2*)(out16 + row * HSZ))[tid] = h;
    }
}

// ---------------- output assembly ----------------
__global__ void __launch_bounds__(256) write_out_kernel(float* __restrict__ out, long out_size)
{
    long i = (long)blockIdx.x * 256 + threadIdx.x;
    if (i >= out_size) return;
    const long G  = (long)BB * HSZ;
    const long ND = (long)BB * NN * HSZ;
    if (i < G) {
        long b = i >> 9;
        long c = i & 511;
        out[i] = g_x[(b * NN + EE) * HSZ + c];
    } else if (i < G + ND) {
        out[i] = g_x[i - G];
    } else {
        out[i] = 1.0f;
    }
}

// ---------------- orchestration ----------------
extern "C" void kernel_launch(void* const* d_in, const int* in_sizes, int n_in,
                              void* d_out, int out_size)
{
    const float* ents = (const float*)d_in[0];
    const int*   rels = (const int*)  d_in[1];
    const int*   adj  = (const int*)  d_in[2];
    const float* renc = (const float*)d_in[3];
    const float* Wq   = (const float*)d_in[4];
    const float* Wk   = (const float*)d_in[5];
    const float* Wv   = (const float*)d_in[6];
    const float* l1w  = (const float*)d_in[7];
    const float* l1b  = (const float*)d_in[8];
    const float* l2w  = (const float*)d_in[9];
    const float* l2b  = (const float*)d_in[10];
    const float* ln1s = (const float*)d_in[11];
    const float* ln1b = (const float*)d_in[12];
    const float* ln2s = (const float*)d_in[13];
    const float* ln2b = (const float*)d_in[14];
    const float* pa   = (const float*)d_in[15];

    float *gx, *go;
    __half *gxh, *gt16, *gh16, *gvt, *gw16, *gw1t, *gw2t;
    cudaGetSymbolAddress((void**)&gx,  g_x);
    cudaGetSymbolAddress((void**)&go,  g_o);
    cudaGetSymbolAddress((void**)&gxh, g_xh);
    cudaGetSymbolAddress((void**)&gt16, g_t16);
    cudaGetSymbolAddress((void**)&gh16, g_h16);
    cudaGetSymbolAddress((void**)&gvt, g_vt);
    cudaGetSymbolAddress((void**)&gw16, g_w16);
    cudaGetSymbolAddress((void**)&gw1t, g_w1t);
    cudaGetSymbolAddress((void**)&gw2t, g_w2t);

    cudaFuncSetAttribute(flash_kernel, cudaFuncAttributeMaxDynamicSharedMemorySize, FL_BYTES);
    cudaFuncSetAttribute(gemm16<true>,  cudaFuncAttributeMaxDynamicSharedMemorySize, G_BYTES);
    cudaFuncSetAttribute(gemm16<false>, cudaFuncAttributeMaxDynamicSharedMemorySize, G_BYTES);

    const long M = MTOT;                            // 16384

    { // gather (fp32 + fp16)
        long tot = M * (HSZ/4);
        gather_kernel<<<(unsigned)((tot + 255) / 256), 256>>>(ents, rels, renc);
    }
    { // bitmask
        long tot = (long)BB * NN * (NN/32);
        mask_kernel<<<(unsigned)((tot + 255) / 256), 256>>>(adj);
    }
    { // pack weights
        long tot = (long)PROP * NQKV * HSZ;
        pack_w_kernel<<<(unsigned)((tot + 255) / 256), 256>>>(Wq, Wk, Wv);
        long tot2 = (long)PROP * DFF * HSZ;
        pack_ffn_kernel<<<(unsigned)((tot2 + 255) / 256), 256>>>(l1w, l2w);
    }

    for (int j = 0; j < PROP; j++) {
        // QKV = xh @ W^T -> g_h16 [M][1536] fp16 (Wq pre-scaled)
        gemm16<true><<<dim3(NQKV/128, (unsigned)(M/128)), 256, G_BYTES>>>(
            gxh, gw16 + (long)j*NQKV*HSZ, gh16, HSZ, HSZ, HSZ, NQKV,
            nullptr, nullptr, nullptr);

        // V transpose -> g_vt
        vtrans_kernel<<<dim3(NN/64, HEADS*2, BB), 256>>>(gh16);

        // flash attention + residual -> g_o fp32
        flash_kernel<<<dim3(NN/128, HEADS, BB), 256, FL_BYTES>>>(gh16, gvt, gx, go);

        // t = LN1(o) -> fp16
        layernorm_kernel<1><<<(unsigned)M, 128>>>(go, nullptr, gt16, ln1s + j*HSZ, ln1b + j*HSZ);

        // h = prelu(t @ l1_w + b) -> g_h16 [M][2048] fp16
        gemm16<true><<<dim3(DFF/128, (unsigned)(M/128)), 256, G_BYTES>>>(
            gt16, gw1t + (long)j*DFF*HSZ, gh16, HSZ, HSZ, HSZ, DFF,
            l1b + (long)j*DFF, pa + (long)j*DFF, nullptr);

        // o = h @ l2_w + b + t -> g_o fp32
        gemm16<false><<<dim3(HSZ/128, (unsigned)(M/128)), 256, G_BYTES>>>(
            gh16, gw2t + (long)j*HSZ*DFF, go, DFF, DFF, DFF, HSZ,
            l2b + (long)j*HSZ, nullptr, gt16);

        // x = LN2(o)
        if (j < PROP - 1)
            layernorm_kernel<2><<<(unsigned)M, 128>>>(go, gx, gxh, ln2s + j*HSZ, ln2b + j*HSZ);
        else
            layernorm_kernel<0><<<(unsigned)M, 128>>>(go, gx, nullptr, ln2s + j*HSZ, ln2b + j*HSZ);
    }

    { // output
        long os = (long)out_size;
        write_out_kernel<<<(unsigned)((os + 255) / 256), 256>>>((float*)d_out, os);
    }
}

// round 13
// speedup vs baseline: 2.6884x; 1.6398x over previous
#include <cuda_runtime.h>
#include <cuda_fp16.h>
#include <float.h>
#include <math.h>

// ---------------- problem constants ----------------
#define BB   16
#define EE   400
#define RR   624
#define NN   1024
#define HSZ  512
#define HEADS 4
#define DK   128
#define DFF  2048
#define PROP 2
#define RTOKS 40
#define NQKV 1536
#define MTOT ((long)BB*NN)

// ---------------- scratch (device globals) ----------------
__device__ float  g_x[(long)BB*NN*HSZ];            // fp32 residual / final out
__device__ float  g_o[(long)BB*NN*HSZ];            // fp32 pre-LN
__device__ __half g_xh[(long)BB*NN*HSZ];           // fp16 activation (QKV A)
__device__ __half g_t16[(long)BB*NN*HSZ];          // fp16 LN1 out (FFN1 A, FFN2 res)
__device__ __half g_h16[(long)BB*NN*DFF];          // fp16 QKV out / FFN1 out
__device__ __half g_vt[(long)BB*HEADS*DK*NN];      // fp16 transposed V
__device__ __half g_w16[(long)PROP*NQKV*HSZ];      // [n][k] packed QKV weights (Wq pre-scaled)
__device__ __half g_w1t[(long)PROP*DFF*HSZ];       // [n][k] l1_w
__device__ __half g_w2t[(long)PROP*HSZ*DFF];       // [n][k] l2_w
__device__ unsigned g_mask[(long)BB*NN*(NN/32)];

// ---------------- helpers ----------------
__device__ __forceinline__ void mma_f16(float* c, const unsigned* a, unsigned b0, unsigned b1) {
    asm volatile(
        "mma.sync.aligned.m16n8k16.row.col.f32.f16.f16.f32 "
        "{%0,%1,%2,%3}, {%4,%5,%6,%7}, {%8,%9}, {%0,%1,%2,%3};\n"
        : "+f"(c[0]), "+f"(c[1]), "+f"(c[2]), "+f"(c[3])
        : "r"(a[0]), "r"(a[1]), "r"(a[2]), "r"(a[3]), "r"(b0), "r"(b1));
}
__device__ __forceinline__ void ldsm4(unsigned& r0, unsigned& r1, unsigned& r2, unsigned& r3,
                                      unsigned addr) {
    asm volatile("ldmatrix.sync.aligned.m8n8.x4.shared.b16 {%0,%1,%2,%3}, [%4];"
                 : "=r"(r0), "=r"(r1), "=r"(r2), "=r"(r3) : "r"(addr));
}
__device__ __forceinline__ unsigned f22h(float lo, float hi) {
    __half2 h = __floats2half2_rn(lo, hi);
    return *(unsigned*)&h;
}
__device__ __forceinline__ void cp16(unsigned dst, const void* src) {
    asm volatile("cp.async.cg.shared.global [%0], [%1], 16;" :: "r"(dst), "l"(src) : "memory");
}
__device__ __forceinline__ void cp_commit() {
    asm volatile("cp.async.commit_group;" ::: "memory");
}

// ---------------- gather: x = concat(ents, renc[rels]) -> fp32 + fp16 ----------------
__global__ void __launch_bounds__(256) gather_kernel(
    const float* __restrict__ ents, const int* __restrict__ rels,
    const float* __restrict__ renc)
{
    long i = (long)blockIdx.x * 256 + threadIdx.x;          // float4 index
    const long TOT = MTOT * (HSZ / 4);
    if (i >= TOT) return;
    int c  = (int)(i & (HSZ/4 - 1));
    long bn = i >> 7;
    int n  = (int)(bn & (NN - 1));
    int b  = (int)(bn >> 10);
    float4 v;
    if (n < EE) {
        v = ((const float4*)ents)[((long)b*EE + n)*(HSZ/4) + c];
    } else {
        int r = rels[b*RR + (n - EE)];
        v = ((const float4*)renc)[(long)r*(HSZ/4) + c];
    }
    ((float4*)g_x)[i] = v;
    uint2 h = make_uint2(f22h(v.x, v.y), f22h(v.z, v.w));
    ((uint2*)g_xh)[i] = h;
}

// ---------------- adj -> bitmask ----------------
__global__ void __launch_bounds__(256) mask_kernel(const int* __restrict__ adj)
{
    long i = (long)blockIdx.x * 256 + threadIdx.x;
    const long TOT = (long)BB * NN * (NN / 32);
    if (i >= TOT) return;
    const int* p = adj + i * 32;
    unsigned m = 0;
    #pragma unroll
    for (int t = 0; t < 8; t++) {
        int4 a = ((const int4*)p)[t];
        m |= (a.x ? 1u : 0u) << (t*4 + 0);
        m |= (a.y ? 1u : 0u) << (t*4 + 1);
        m |= (a.z ? 1u : 0u) << (t*4 + 2);
        m |= (a.w ? 1u : 0u) << (t*4 + 3);
    }
    g_mask[i] = m;
}

// ---------------- coalesced transpose-pack: [K][N] fp32 -> [N][K] fp16 ----------------
__global__ void __launch_bounds__(256) tpack_kernel(
    const float* __restrict__ in, __half* __restrict__ out,
    int Kd, int Nd, long inStrideJ, long outStrideJ, int outLd, float scale)
{
    __shared__ float st[32][33];
    int j = blockIdx.z;
    const float* I = in + (long)j * inStrideJ;
    __half* O = out + (long)j * outStrideJ;
    int n0 = blockIdx.x * 32, k0 = blockIdx.y * 32;
    int tid = threadIdx.x;
    int c = tid & 31, r0 = tid >> 5;
    #pragma unroll
    for (int t = 0; t < 4; t++) {
        int k = r0 + t * 8;
        st[k][c] = I[(long)(k0 + k) * Nd + n0 + c];
    }
    __syncthreads();
    #pragma unroll
    for (int t = 0; t < 4; t++) {
        int n = r0 + t * 8;
        O[(long)(n0 + n) * outLd + k0 + c] = __float2half_rn(st[c][n] * scale);
    }
}

// ---------------- V transpose: qkv[M][1536] V-part -> vt[b][h][dk][NN] ----------------
__global__ void __launch_bounds__(256) vtrans_kernel(const __half* __restrict__ qkv)
{
    __shared__ __half st[64][72];
    int stile = blockIdx.x;
    int hd = blockIdx.y;
    int b = blockIdx.z;
    int h = hd >> 1, dt = hd & 1;
    int s0 = stile * 64, d0 = dt * 64;
    int tid = threadIdx.x;

    #pragma unroll
    for (int t = 0; t < 8; t++) {
        int idx = tid + t * 256;
        int r = idx >> 5, c2 = idx & 31;
        const __half* src = qkv + ((long)(b*NN + s0 + r)) * NQKV + 1024 + h*DK + d0 + 2*c2;
        *(__half2*)&st[r][2*c2] = *(const __half2*)src;
    }
    __syncthreads();
    #pragma unroll
    for (int t = 0; t < 8; t++) {
        int idx = tid + t * 256;
        int d = idx >> 5, s2 = idx & 31;
        __half2 o;
        o.x = st[2*s2][d];
        o.y = st[2*s2 + 1][d];
        __half* dst = g_vt + ((long)((b*HEADS + h)*DK + d0 + d)) * NN + s0 + 2*s2;
        *(__half2*)dst = o;
    }
}

// ---------------- fused flash attention fp16 (ldmatrix fragments) ----------------
#define FL_STR 68
#define FL_W   (128 * FL_STR)
#define FL_BYTES (3 * FL_W * 4)
#define FL_NT  (NN / 128)

__global__ void __launch_bounds__(256) flash_kernel(
    const __half* __restrict__ QKV, const __half* __restrict__ VT,
    const float* __restrict__ X, float* __restrict__ O)
{
    extern __shared__ unsigned sm[];
    unsigned sbase = (unsigned)__cvta_generic_to_shared(sm);
    const unsigned qbase = sbase;
    const unsigned kbase = sbase + FL_W * 4;
    const unsigned vbase = sbase + 2 * FL_W * 4;

    int qt = blockIdx.x, h = blockIdx.y, b = blockIdx.z;
    int tid = threadIdx.x, warp = tid >> 5, lane = tid & 31;
    int gid = lane >> 2, tig = lane & 3;
    int jj = lane >> 3, rl = lane & 7;      // ldmatrix lane decomposition

    const long baserow = (long)b * NN;
    const __half* Qsrc  = QKV + (baserow + qt*128) * NQKV + h*DK;
    const __half* Kbase = QKV + baserow * NQKV + 512 + h*DK;
    const __half* Vbase = VT + ((long)(b*HEADS + h)) * DK * NN;

    auto cp_tile = [&](unsigned dstW, const __half* src, int srcld) {
        #pragma unroll
        for (int t = 0; t < 8; t++) {
            int i = tid + t * 256;
            int r = i >> 4, c = i & 15;
            cp16(sbase + (dstW + r * FL_STR + c * 4) * 4, src + (long)r * srcld + c * 8);
        }
    };

    cp_tile(0, Qsrc, NQKV);           cp_commit();
    cp_tile(FL_W, Kbase, NQKV);       cp_commit();
    cp_tile(2*FL_W, Vbase, NN);       cp_commit();

    float acc_o[16][4];
    #pragma unroll
    for (int nt = 0; nt < 16; nt++)
        #pragma unroll
        for (int i = 0; i < 4; i++) acc_o[nt][i] = 0.f;

    float m0 = -INFINITY, m1 = -INFINITY, l0 = 0.f, l1 = 0.f;
    const unsigned* mrow0 = g_mask + ((long)b*NN + qt*128 + warp*16 + gid) * (NN/32);
    const unsigned* mrow1 = mrow0 + 8 * (NN/32);

    float acc_s[16][4];

    for (int j = 0; j < FL_NT; j++) {
        asm volatile("cp.async.wait_group 1;" ::: "memory");   // K_j ready
        __syncthreads();

        #pragma unroll
        for (int nt = 0; nt < 16; nt++)
            #pragma unroll
            for (int i = 0; i < 4; i++) acc_s[nt][i] = 0.f;

        // S = Q @ K^T : 8 k16 steps; fragments via ldmatrix
        #pragma unroll
        for (int ks = 0; ks < 8; ks++) {
            unsigned a[4];
            {
                int row = warp*16 + ((jj & 1) << 3) + rl;
                ldsm4(a[0], a[1], a[2], a[3],
                      qbase + (row * FL_STR + ks*8 + ((jj >> 1) << 2)) * 4);
            }
            #pragma unroll
            for (int ntp = 0; ntp < 8; ntp++) {
                int row = ntp*16 + ((jj >> 1) << 3) + rl;
                unsigned b0, b1, b2, b3;
                ldsm4(b0, b1, b2, b3,
                      kbase + (row * FL_STR + ks*8 + ((jj & 1) << 2)) * 4);
                mma_f16(acc_s[2*ntp],   a, b0, b1);
                mma_f16(acc_s[2*ntp+1], a, b2, b3);
            }
        }

        __syncthreads();
        if (j + 1 < FL_NT) {
            cp_tile(FL_W, Kbase + (long)(j+1)*128 * NQKV, NQKV);
            cp_commit();
        }

        // mask + online softmax
        unsigned mw0[4], mw1[4];
        #pragma unroll
        for (int w = 0; w < 4; w++) { mw0[w] = mrow0[j*4 + w]; mw1[w] = mrow1[j*4 + w]; }

        float tm0 = -INFINITY, tm1 = -INFINITY;
        #pragma unroll
        for (int nt = 0; nt < 16; nt++) {
            int c0 = nt*8 + tig*2;
            unsigned w = nt >> 2;
            int bi = c0 & 31;
            acc_s[nt][0] = ((mw0[w] >> bi)     & 1) ? acc_s[nt][0] : -1e30f;
            acc_s[nt][1] = ((mw0[w] >> (bi+1)) & 1) ? acc_s[nt][1] : -1e30f;
            acc_s[nt][2] = ((mw1[w] >> bi)     & 1) ? acc_s[nt][2] : -1e30f;
            acc_s[nt][3] = ((mw1[w] >> (bi+1)) & 1) ? acc_s[nt][3] : -1e30f;
            tm0 = fmaxf(tm0, fmaxf(acc_s[nt][0], acc_s[nt][1]));
            tm1 = fmaxf(tm1, fmaxf(acc_s[nt][2], acc_s[nt][3]));
        }
        tm0 = fmaxf(tm0, __shfl_xor_sync(0xffffffffu, tm0, 1));
        tm0 = fmaxf(tm0, __shfl_xor_sync(0xffffffffu, tm0, 2));
        tm1 = fmaxf(tm1, __shfl_xor_sync(0xffffffffu, tm1, 1));
        tm1 = fmaxf(tm1, __shfl_xor_sync(0xffffffffu, tm1, 2));

        float nm0 = fmaxf(m0, tm0), nm1 = fmaxf(m1, tm1);
        float f0 = __expf(m0 - nm0), f1 = __expf(m1 - nm1);

        float sum0 = 0.f, sum1 = 0.f;
        #pragma unroll
        for (int nt = 0; nt < 16; nt++) {
            float p0 = __expf(acc_s[nt][0] - nm0);
            float p1 = __expf(acc_s[nt][1] - nm0);
            float p2 = __expf(acc_s[nt][2] - nm1);
            float p3 = __expf(acc_s[nt][3] - nm1);
            sum0 += p0 + p1; sum1 += p2 + p3;
            acc_s[nt][0] = p0; acc_s[nt][1] = p1;
            acc_s[nt][2] = p2; acc_s[nt][3] = p3;
        }
        sum0 += __shfl_xor_sync(0xffffffffu, sum0, 1);
        sum0 += __shfl_xor_sync(0xffffffffu, sum0, 2);
        sum1 += __shfl_xor_sync(0xffffffffu, sum1, 1);
        sum1 += __shfl_xor_sync(0xffffffffu, sum1, 2);

        l0 = l0 * f0 + sum0;  l1 = l1 * f1 + sum1;
        m0 = nm0;  m1 = nm1;
        #pragma unroll
        for (int nt = 0; nt < 16; nt++) {
            acc_o[nt][0] *= f0; acc_o[nt][1] *= f0;
            acc_o[nt][2] *= f1; acc_o[nt][3] *= f1;
        }

        if (j + 1 < FL_NT) asm volatile("cp.async.wait_group 1;" ::: "memory");
        else               asm volatile("cp.async.wait_group 0;" ::: "memory");
        __syncthreads();

        // O += P @ V : P acc-layout == fp16 A-frag layout; B via ldmatrix
        #pragma unroll
        for (int ks = 0; ks < 8; ks++) {
            unsigned a[4];
            a[0] = f22h(acc_s[2*ks][0],   acc_s[2*ks][1]);
            a[1] = f22h(acc_s[2*ks][2],   acc_s[2*ks][3]);
            a[2] = f22h(acc_s[2*ks+1][0], acc_s[2*ks+1][1]);
            a[3] = f22h(acc_s[2*ks+1][2], acc_s[2*ks+1][3]);
            #pragma unroll
            for (int ntp = 0; ntp < 8; ntp++) {
                int row = ntp*16 + ((jj >> 1) << 3) + rl;
                unsigned b0, b1, b2, b3;
                ldsm4(b0, b1, b2, b3,
                      vbase + (row * FL_STR + ks*8 + ((jj & 1) << 2)) * 4);
                mma_f16(acc_o[2*ntp],   a, b0, b1);
                mma_f16(acc_o[2*ntp+1], a, b2, b3);
            }
        }

        if (j + 1 < FL_NT) {
            __syncthreads();
            cp_tile(2*FL_W, Vbase + (j+1)*128, NN);
            cp_commit();
        }
    }

    float inv0 = 1.f / l0, inv1 = 1.f / l1;
    long rbase = (baserow + qt*128 + warp*16 + gid) * HSZ + h*DK;
    #pragma unroll
    for (int nt = 0; nt < 16; nt++) {
        int c0 = nt*8 + tig*2;
        float2 x0 = *(const float2*)(X + rbase + c0);
        float2 x1 = *(const float2*)(X + rbase + 8*HSZ + c0);
        float2 o0 = make_float2(acc_o[nt][0]*inv0 + x0.x, acc_o[nt][1]*inv0 + x0.y);
        float2 o1 = make_float2(acc_o[nt][2]*inv1 + x1.x, acc_o[nt][3]*inv1 + x1.y);
        *(float2*)(O + rbase + c0)         = o0;
        *(float2*)(O + rbase + 8*HSZ + c0) = o1;
    }
}

// ---------------- fp16 GEMM (ldmatrix): C[m][n] = A[m][k] @ B[n][k]^T, k-chunk 64 ----------------
#define GSTR 36
#define G_AW (128 * GSTR)
#define G_STG (2 * G_AW)
#define G_BYTES (2 * G_STG * 4)

template<bool OUT16>
__global__ void __launch_bounds__(256, 2) gemm16(
    const __half* __restrict__ A, const __half* __restrict__ B, void* __restrict__ Cv,
    int K, int lda, int ldb, int ldc,
    const float* __restrict__ bias,
    const float* __restrict__ prelu,
    const __half* __restrict__ res)
{
    extern __shared__ unsigned gsm[];
    unsigned sbase = (unsigned)__cvta_generic_to_shared(gsm);

    int bm = blockIdx.y << 7;
    int bn = blockIdx.x << 7;

    int tid  = threadIdx.x;
    int warp = tid >> 5, lane = tid & 31;
    int wm = warp >> 1, wn = warp & 1;
    int gid = lane >> 2, tig = lane & 3;
    int jj = lane >> 3, rl = lane & 7;

    auto load_chunk = [&](int stage, int c) {
        unsigned aw = sbase + (stage * G_STG) * 4;
        const __half* pa = A + (long)bm * lda + c * 64;
        #pragma unroll
        for (int t = 0; t < 4; t++) {
            int i = tid + t * 256;
            int r = i >> 3, cc = i & 7;
            cp16(aw + (r * GSTR + cc * 4) * 4, pa + (long)r * lda + cc * 8);
        }
        unsigned bw = sbase + (stage * G_STG + G_AW) * 4;
        const __half* pb = B + (long)bn * ldb + c * 64;
        #pragma unroll
        for (int t = 0; t < 4; t++) {
            int i = tid + t * 256;
            int r = i >> 3, cc = i & 7;
            cp16(bw + (r * GSTR + cc * 4) * 4, pb + (long)r * ldb + cc * 8);
        }
        cp_commit();
    };

    float acc[2][8][4];
    #pragma unroll
    for (int mt = 0; mt < 2; mt++)
        #pragma unroll
        for (int nt = 0; nt < 8; nt++)
            #pragma unroll
            for (int i = 0; i < 4; i++) acc[mt][nt][i] = 0.f;

    const int nch = K >> 6;
    load_chunk(0, 0);

    for (int c = 0; c < nch; c++) {
        int cur = c & 1;
        if (c + 1 < nch) {
            load_chunk(cur ^ 1, c + 1);
            asm volatile("cp.async.wait_group 1;" ::: "memory");
        } else {
            asm volatile("cp.async.wait_group 0;" ::: "memory");
        }
        __syncthreads();

        unsigned abase = sbase + (cur * G_STG) * 4;
        unsigned bbase = abase + G_AW * 4;

        #pragma unroll
        for (int ks = 0; ks < 4; ks++) {
            unsigned a[2][4];
            #pragma unroll
            for (int mt = 0; mt < 2; mt++) {
                int row = wm*32 + mt*16 + ((jj & 1) << 3) + rl;
                ldsm4(a[mt][0], a[mt][1], a[mt][2], a[mt][3],
                      abase + (row * GSTR + ks*8 + ((jj >> 1) << 2)) * 4);
            }
            #pragma unroll
            for (int ntp = 0; ntp < 4; ntp++) {
                int row = wn*64 + ntp*16 + ((jj >> 1) << 3) + rl;
                unsigned b0, b1, b2, b3;
                ldsm4(b0, b1, b2, b3,
                      bbase + (row * GSTR + ks*8 + ((jj & 1) << 2)) * 4);
                mma_f16(acc[0][2*ntp],   a[0], b0, b1);
                mma_f16(acc[1][2*ntp],   a[1], b0, b1);
                mma_f16(acc[0][2*ntp+1], a[0], b2, b3);
                mma_f16(acc[1][2*ntp+1], a[1], b2, b3);
            }
        }
        __syncthreads();
    }

    // epilogue
    #pragma unroll
    for (int mt = 0; mt < 2; mt++) {
        int r0 = bm + wm * 32 + mt * 16 + gid;
        #pragma unroll
        for (int nt = 0; nt < 8; nt++) {
            int c0 = bn + wn * 64 + nt * 8 + tig * 2;
            float v0 = acc[mt][nt][0];
            float v1 = acc[mt][nt][1];
            float v2 = acc[mt][nt][2];
            float v3 = acc[mt][nt][3];
            if (bias) {
                float b0v = bias[c0], b1v = bias[c0 + 1];
                v0 += b0v; v1 += b1v; v2 += b0v; v3 += b1v;
            }
            if (prelu) {
                float p0 = prelu[c0], p1 = prelu[c0 + 1];
                v0 = v0 > 0.f ? v0 : v0 * p0;
                v1 = v1 > 0.f ? v1 : v1 * p1;
                v2 = v2 > 0.f ? v2 : v2 * p0;
                v3 = v3 > 0.f ? v3 : v3 * p1;
            }
            if (res) {
                __half2 q0 = *(const __half2*)(res + (long)r0 * ldc + c0);
                __half2 q1 = *(const __half2*)(res + (long)(r0 + 8) * ldc + c0);
                v0 += __half2float(q0.x); v1 += __half2float(q0.y);
                v2 += __half2float(q1.x); v3 += __half2float(q1.y);
            }
            if (OUT16) {
                __half* C = (__half*)Cv;
                *(unsigned*)(C + (long)r0 * ldc + c0)       = f22h(v0, v1);
                *(unsigned*)(C + (long)(r0 + 8) * ldc + c0) = f22h(v2, v3);
            } else {
                float* C = (float*)Cv;
                *(float2*)(C + (long)r0 * ldc + c0)       = make_float2(v0, v1);
                *(float2*)(C + (long)(r0 + 8) * ldc + c0) = make_float2(v2, v3);
            }
        }
    }
}

// ---------------- layer norm: fp32 in; MODE 0=fp32 only, 1=fp16 only, 2=both ----------------
template<int MODE>
__global__ void __launch_bounds__(128) layernorm_kernel(
    const float* __restrict__ in, float* __restrict__ out32, __half* __restrict__ out16,
    const float* __restrict__ gamma, const float* __restrict__ beta)
{
    long row = blockIdx.x;
    int tid = threadIdx.x, lane = tid & 31, wid = tid >> 5;
    float4 v = ((const float4*)(in + row * HSZ))[tid];

    __shared__ float red[8];
    float s = v.x + v.y + v.z + v.w;
    #pragma unroll
    for (int o = 16; o > 0; o >>= 1) s += __shfl_xor_sync(0xffffffffu, s, o);
    if (lane == 0) red[wid] = s;
    __syncthreads();
    float mu = (red[0] + red[1] + red[2] + red[3]) * (1.f / HSZ);

    float dx = v.x - mu, dy = v.y - mu, dz = v.z - mu, dw = v.w - mu;
    float q = dx*dx + dy*dy + dz*dz + dw*dw;
    #pragma unroll
    for (int o = 16; o > 0; o >>= 1) q += __shfl_xor_sync(0xffffffffu, q, o);
    if (lane == 0) red[4 + wid] = q;
    __syncthreads();
    float var = (red[4] + red[5] + red[6] + red[7]) * (1.f / HSZ);
    float rstd = rsqrtf(var + 1e-5f);

    float4 g = ((const float4*)gamma)[tid];
    float4 bb = ((const float4*)beta)[tid];
    float4 o4;
    o4.x = dx * rstd * g.x + bb.x;
    o4.y = dy * rstd * g.y + bb.y;
    o4.z = dz * rstd * g.z + bb.z;
    o4.w = dw * rstd * g.w + bb.w;
    if (MODE != 1) ((float4*)(out32 + row * HSZ))[tid] = o4;
    if (MODE != 0) {
        uint2 h = make_uint2(f22h(o4.x, o4.y), f22h(o4.z, o4.w));
        ((uint2*)(out16 + row * HSZ))[tid] = h;
    }
}

// ---------------- output assembly ----------------
__global__ void __launch_bounds__(256) write_out_kernel(float* __restrict__ out, long out_size)
{
    long i = (long)blockIdx.x * 256 + threadIdx.x;
    if (i >= out_size) return;
    const long G  = (long)BB * HSZ;
    const long ND = (long)BB * NN * HSZ;
    if (i < G) {
        long b = i >> 9;
        long c = i & 511;
        out[i] = g_x[(b * NN + EE) * HSZ + c];
    } else if (i < G + ND) {
        out[i] = g_x[i - G];
    } else {
        out[i] = 1.0f;
    }
}

// ---------------- orchestration ----------------
extern "C" void kernel_launch(void* const* d_in, const int* in_sizes, int n_in,
                              void* d_out, int out_size)
{
    const float* ents = (const float*)d_in[0];
    const int*   rels = (const int*)  d_in[1];
    const int*   adj  = (const int*)  d_in[2];
    const float* renc = (const float*)d_in[3];
    const float* Wq   = (const float*)d_in[4];
    const float* Wk   = (const float*)d_in[5];
    const float* Wv   = (const float*)d_in[6];
    const float* l1w  = (const float*)d_in[7];
    const float* l1b  = (const float*)d_in[8];
    const float* l2w  = (const float*)d_in[9];
    const float* l2b  = (const float*)d_in[10];
    const float* ln1s = (const float*)d_in[11];
    const float* ln1b = (const float*)d_in[12];
    const float* ln2s = (const float*)d_in[13];
    const float* ln2b = (const float*)d_in[14];
    const float* pa   = (const float*)d_in[15];

    float *gx, *go;
    __half *gxh, *gt16, *gh16, *gvt, *gw16, *gw1t, *gw2t;
    cudaGetSymbolAddress((void**)&gx,  g_x);
    cudaGetSymbolAddress((void**)&go,  g_o);
    cudaGetSymbolAddress((void**)&gxh, g_xh);
    cudaGetSymbolAddress((void**)&gt16, g_t16);
    cudaGetSymbolAddress((void**)&gh16, g_h16);
    cudaGetSymbolAddress((void**)&gvt, g_vt);
    cudaGetSymbolAddress((void**)&gw16, g_w16);
    cudaGetSymbolAddress((void**)&gw1t, g_w1t);
    cudaGetSymbolAddress((void**)&gw2t, g_w2t);

    cudaFuncSetAttribute(flash_kernel, cudaFuncAttributeMaxDynamicSharedMemorySize, FL_BYTES);
    cudaFuncSetAttribute(gemm16<true>,  cudaFuncAttributeMaxDynamicSharedMemorySize, G_BYTES);
    cudaFuncSetAttribute(gemm16<false>, cudaFuncAttributeMaxDynamicSharedMemorySize, G_BYTES);

    const long M = MTOT;                            // 16384
    const float qscale = 0.04419417382415922f;      // 1/sqrt(512)

    { // gather (fp32 + fp16)
        long tot = M * (HSZ/4);
        gather_kernel<<<(unsigned)((tot + 255) / 256), 256>>>(ents, rels, renc);
    }
    { // bitmask
        long tot = (long)BB * NN * (NN/32);
        mask_kernel<<<(unsigned)((tot + 255) / 256), 256>>>(adj);
    }
    { // coalesced weight packs: [k][n] fp32 -> [n][k] fp16
        // Wq (scaled), Wk, Wv into g_w16 at n-offsets 0 / 512 / 1024
        tpack_kernel<<<dim3(512/32, 512/32, PROP), 256>>>(
            Wq, gw16,            512, 512, (long)512*512, (long)NQKV*HSZ, HSZ, qscale);
        tpack_kernel<<<dim3(512/32, 512/32, PROP), 256>>>(
            Wk, gw16 + 512*HSZ,  512, 512, (long)512*512, (long)NQKV*HSZ, HSZ, 1.f);
        tpack_kernel<<<dim3(512/32, 512/32, PROP), 256>>>(
            Wv, gw16 + 1024*HSZ, 512, 512, (long)512*512, (long)NQKV*HSZ, HSZ, 1.f);
        // l1_w [512][2048] -> g_w1t [2048][512]
        tpack_kernel<<<dim3(DFF/32, 512/32, PROP), 256>>>(
            l1w, gw1t, 512, DFF, (long)512*DFF, (long)DFF*HSZ, HSZ, 1.f);
        // l2_w [2048][512] -> g_w2t [512][2048]
        tpack_kernel<<<dim3(512/32, DFF/32, PROP), 256>>>(
            l2w, gw2t, DFF, 512, (long)DFF*512, (long)HSZ*DFF, DFF, 1.f);
    }

    for (int j = 0; j < PROP; j++) {
        // QKV = xh @ W^T -> g_h16 [M][1536] fp16 (Wq pre-scaled)
        gemm16<true><<<dim3(NQKV/128, (unsigned)(M/128)), 256, G_BYTES>>>(
            gxh, gw16 + (long)j*NQKV*HSZ, gh16, HSZ, HSZ, HSZ, NQKV,
            nullptr, nullptr, nullptr);

        // V transpose -> g_vt
        vtrans_kernel<<<dim3(NN/64, HEADS*2, BB), 256>>>(gh16);

        // flash attention + residual -> g_o fp32
        flash_kernel<<<dim3(NN/128, HEADS, BB), 256, FL_BYTES>>>(gh16, gvt, gx, go);

        // t = LN1(o) -> fp16
        layernorm_kernel<1><<<(unsigned)M, 128>>>(go, nullptr, gt16, ln1s + j*HSZ, ln1b + j*HSZ);

        // h = prelu(t @ l1_w + b) -> g_h16 [M][2048] fp16
        gemm16<true><<<dim3(DFF/128, (unsigned)(M/128)), 256, G_BYTES>>>(
            gt16, gw1t + (long)j*DFF*HSZ, gh16, HSZ, HSZ, HSZ, DFF,
            l1b + (long)j*DFF, pa + (long)j*DFF, nullptr);

        // o = h @ l2_w + b + t -> g_o fp32
        gemm16<false><<<dim3(HSZ/128, (unsigned)(M/128)), 256, G_BYTES>>>(
            gh16, gw2t + (long)j*HSZ*DFF, go, DFF, DFF, DFF, HSZ,
            l2b + (long)j*HSZ, nullptr, gt16);

        // x = LN2(o)
        if (j < PROP - 1)
            layernorm_kernel<2><<<(unsigned)M, 128>>>(go, gx, gxh, ln2s + j*HSZ, ln2b + j*HSZ);
        else
            layernorm_kernel<0><<<(unsigned)M, 128>>>(go, gx, nullptr, ln2s + j*HSZ, ln2b + j*HSZ);
    }

    { // output
        long os = (long)out_size;
        write_out_kernel<<<(unsigned)((os + 255) / 256), 256>>>((float*)d_out, os);
    }
}